// round 8
// baseline (speedup 1.0000x reference)
#include <cuda_runtime.h>
#include <cstdint>
#include <cstddef>

// Problem dims
#define VN 128
#define HN 512
#define BN 512
#define SN 256
#define KC 16   // K-chunk per smem stage

// Static scratch (module-load allocated; no runtime allocation)
__device__ float g_hs_f[(size_t)(SN + 1) * BN * HN];  // forward h history, slot 0 = h0 (zeros)
__device__ float g_hs_b[(size_t)(SN + 1) * BN * HN];  // backward-scan h history
__device__ float g_c[2 * BN * HN];                    // cell state, [dir][b][j]

__device__ __forceinline__ float to_tf32(float x) {
    float r;
    asm("cvt.rna.tf32.f32 %0, %1;" : "=f"(r) : "f"(x));
    return r;
}

__device__ __forceinline__ float4 cvt4(float4 v) {
    return make_float4(to_tf32(v.x), to_tf32(v.y), to_tf32(v.z), to_tf32(v.w));
}

__device__ __forceinline__ void mma_tf32(float* d, const unsigned* a, const unsigned* b) {
    asm volatile(
        "mma.sync.aligned.m16n8k8.row.col.f32.tf32.tf32.f32 "
        "{%0,%1,%2,%3}, {%4,%5,%6,%7}, {%8,%9}, {%0,%1,%2,%3};\n"
        : "+f"(d[0]), "+f"(d[1]), "+f"(d[2]), "+f"(d[3])
        : "r"(a[0]), "r"(a[1]), "r"(a[2]), "r"(a[3]),
          "r"(b[0]), "r"(b[1]));
}

__device__ __forceinline__ float sigmf(float x) { return 1.0f / (1.0f + expf(-x)); }

// Store one staged K-chunk (reg -> smem). Row stride 20 floats (pad 4) => conflict-free frags.
__device__ __forceinline__ void sts_chunk(float* As, float* Bs, int lrow, int lhalf,
                                          float4 ra0, float4 ra1, float4 rb0, float4 rb1) {
    *(float4*)(As + lrow * 20 + lhalf * 8)     = ra0;
    *(float4*)(As + lrow * 20 + lhalf * 8 + 4) = ra1;
    *(float4*)(Bs + lrow * 20 + lhalf * 8)     = rb0;
    *(float4*)(Bs + lrow * 20 + lhalf * 8 + 4) = rb1;
}

// 16 m16n8k8 MMAs x 2 k-steps over the staged KC=16 chunk. Warp tile 64x32.
__device__ __forceinline__ void compute_chunk(const float* As, const float* Bs,
                                              int wm, int wn, int gr, int q,
                                              float acc[4][4][4]) {
#pragma unroll
    for (int ks = 0; ks < 2; ks++) {
        const int kk = ks * 8;
        unsigned af[4][4], bf[4][2];
#pragma unroll
        for (int tm = 0; tm < 4; tm++) {
            int r = wm * 64 + tm * 16 + gr;
            int c = kk + q;
            af[tm][0] = __float_as_uint(As[r * 20 + c]);
            af[tm][1] = __float_as_uint(As[(r + 8) * 20 + c]);
            af[tm][2] = __float_as_uint(As[r * 20 + c + 4]);
            af[tm][3] = __float_as_uint(As[(r + 8) * 20 + c + 4]);
        }
#pragma unroll
        for (int tn = 0; tn < 4; tn++) {
            int n = wn * 32 + tn * 8 + gr;
            bf[tn][0] = __float_as_uint(Bs[n * 20 + kk + q]);
            bf[tn][1] = __float_as_uint(Bs[n * 20 + kk + q + 4]);
        }
#pragma unroll
        for (int tm = 0; tm < 4; tm++)
#pragma unroll
            for (int tn = 0; tn < 4; tn++)
                mma_tf32(acc[tm][tn], af[tm], bf[tn]);
    }
}

__global__ void init_kernel() {
    int i = blockIdx.x * blockDim.x + threadIdx.x;
    if (i < BN * HN) { g_hs_f[i] = 0.f; g_hs_b[i] = 0.f; }
    if (i < 2 * BN * HN) g_c[i] = 0.f;
}

// One recurrence step, both directions (blockIdx.z). CTA tile: 128 batch rows x 32 neurons
// (x 4 gates = 128 GEMM columns), K = 640 = 512 (h_prev) + 128 (one-hot x_t folded in).
__global__ __launch_bounds__(256) void step_kernel(
    int t, const int* __restrict__ x,
    const float* __restrict__ Wx_f, const float* __restrict__ Wh_f,
    const float* __restrict__ bx_f, const float* __restrict__ bh_f,
    const float* __restrict__ Wx_b, const float* __restrict__ Wh_b,
    const float* __restrict__ bx_b, const float* __restrict__ bh_b) {
    __shared__ __align__(16) float As[128 * 20];
    __shared__ __align__(16) float Bs[128 * 20];
    __shared__ float bsum[128];

    const int tid = threadIdx.x;
    const int d = blockIdx.z;
    const int b0 = blockIdx.x * 128;
    const int j0 = blockIdx.y * 32;
    const int t_eff = d ? (SN - 1 - t) : t;

    const float* __restrict__ Wx  = d ? Wx_b : Wx_f;
    const float* __restrict__ Wh  = d ? Wh_b : Wh_f;
    const float* __restrict__ bxp = d ? bx_b : bx_f;
    const float* __restrict__ bhp = d ? bh_b : bh_f;
    float* hs = d ? g_hs_b : g_hs_f;
    float* cst = g_c + (size_t)d * BN * HN;
    const float* hprev = hs + (size_t)t * BN * HN;
    float* hout = hs + (size_t)(t + 1) * BN * HN;

    if (tid < 128) {
        int jj = tid >> 2, gate = tid & 3, j = j0 + jj;
        bsum[tid] = bxp[gate * HN + j] + bhp[gate * HN + j];
    }

    const int lrow = tid >> 1;   // 0..127 (loader row)
    const int lhalf = tid & 1;   // which 8-float half of the 16-wide chunk
    const int warp = tid >> 5, lane = tid & 31;
    const int wm = warp >> 2, wn = warp & 3;
    const int gr = lane >> 2, q = lane & 3;

    // B row n -> (neuron jj, gate): n = jj*4 + gate so each lane-pair owns all 4 gates of a cell
    const int jjB = lrow >> 2, gateB = lrow & 3, jB = j0 + jjB;
    const float* whRow = Wh + ((size_t)gateB * HN + jB) * HN;
    const float* wxRow = Wx + ((size_t)gateB * HN + jB) * VN;
    const float* aRow  = hprev + (size_t)(b0 + lrow) * HN;
    const int xv = x[(b0 + lrow) * SN + t_eff];

    float acc[4][4][4];
#pragma unroll
    for (int i = 0; i < 4; i++)
#pragma unroll
        for (int jx = 0; jx < 4; jx++)
#pragma unroll
            for (int kx = 0; kx < 4; kx++) acc[i][jx][kx] = 0.f;

    float4 ra0, ra1, rb0, rb1;

    // --- chunk loaders (global -> regs, tf32-converted) ---
#define LOAD_CHUNK(kc)                                                           \
    {                                                                            \
        int k = (kc) * KC + lhalf * 8;                                           \
        if (k < 512) {                                                           \
            ra0 = cvt4(*(const float4*)(aRow + k));                              \
            ra1 = cvt4(*(const float4*)(aRow + k + 4));                          \
        } else {                                                                 \
            int kk = k - 512;                                                    \
            ra0 = make_float4(xv == kk + 0 ? 1.f : 0.f, xv == kk + 1 ? 1.f : 0.f,\
                              xv == kk + 2 ? 1.f : 0.f, xv == kk + 3 ? 1.f : 0.f);\
            ra1 = make_float4(xv == kk + 4 ? 1.f : 0.f, xv == kk + 5 ? 1.f : 0.f,\
                              xv == kk + 6 ? 1.f : 0.f, xv == kk + 7 ? 1.f : 0.f);\
        }                                                                        \
        const float* srcB = (k < 512) ? (whRow + k) : (wxRow + (k - 512));       \
        rb0 = cvt4(*(const float4*)(srcB));                                      \
        rb1 = cvt4(*(const float4*)(srcB + 4));                                  \
    }

    LOAD_CHUNK(0);
    sts_chunk(As, Bs, lrow, lhalf, ra0, ra1, rb0, rb1);
    __syncthreads();

    const int NK = 640 / KC;  // 40
    for (int kc = 0; kc < NK; kc++) {
        bool more = (kc + 1 < NK);
        if (more) LOAD_CHUNK(kc + 1);
        compute_chunk(As, Bs, wm, wn, gr, q, acc);
        __syncthreads();
        if (more) {
            sts_chunk(As, Bs, lrow, lhalf, ra0, ra1, rb0, rb1);
            __syncthreads();
        }
    }
#undef LOAD_CHUNK

    // --- epilogue: gates + cell update. Lane pair (l, l^1) exchanges to gather all 4 gates. ---
#pragma unroll
    for (int tm = 0; tm < 4; tm++) {
        int rbase = b0 + wm * 64 + tm * 16 + gr;
#pragma unroll
        for (int tn = 0; tn < 4; tn++) {
            float c0 = acc[tm][tn][0], c1 = acc[tm][tn][1];
            float c2 = acc[tm][tn][2], c3 = acc[tm][tn][3];
            float e0 = __shfl_xor_sync(0xffffffffu, c0, 1);
            float e1 = __shfl_xor_sync(0xffffffffu, c1, 1);
            float e2 = __shfl_xor_sync(0xffffffffu, c2, 1);
            float e3 = __shfl_xor_sync(0xffffffffu, c3, 1);
            float iv, fv, ov, gv;
            int brow;
            if ((q & 1) == 0) { iv = c0; fv = c1; ov = e0; gv = e1; brow = rbase; }
            else              { iv = e2; fv = e3; ov = c2; gv = c3; brow = rbase + 8; }
            int jj4 = wn * 32 + tn * 8 + (q >> 1) * 4;
            float4 bs = *(const float4*)&bsum[jj4];
            float gi = sigmf(iv + bs.x);
            float gf = sigmf(fv + bs.y);
            float go = sigmf(ov + bs.z);
            float gg = tanhf(gv + bs.w);
            size_t ci = (size_t)brow * HN + (size_t)(j0 + (jj4 >> 2));
            float cn = gf * cst[ci] + gi * gg;
            cst[ci] = cn;
            hout[ci] = go * tanhf(cn);
        }
    }
}

// Final FC: y[b,s,v] = [hf(s) | hb(s)] . Wfc[v,:] + bfc[v].  M = S*B, N = V = 128, K = 1024.
__global__ __launch_bounds__(256) void fc_kernel(const float* __restrict__ Wfc,
                                                 const float* __restrict__ bfc,
                                                 float* __restrict__ y) {
    __shared__ __align__(16) float As[128 * 20];
    __shared__ __align__(16) float Bs[128 * 20];
    __shared__ float bsh[128];

    const int tid = threadIdx.x;
    const int mt = blockIdx.x;       // 1024 CTAs: 256 s values x 4 batch tiles
    const int s = mt >> 2;
    const int b0 = (mt & 3) * 128;

    const float* Af = g_hs_f + (size_t)(s + 1) * BN * HN;   // hf[s]
    const float* Ab = g_hs_b + (size_t)(SN - s) * BN * HN;  // hb[s] (un-reversed)

    if (tid < 128) bsh[tid] = bfc[tid];

    const int lrow = tid >> 1, lhalf = tid & 1;
    const int warp = tid >> 5, lane = tid & 31;
    const int wm = warp >> 2, wn = warp & 3;
    const int gr = lane >> 2, q = lane & 3;

    const float* afRow = Af + (size_t)(b0 + lrow) * HN;
    const float* abRow = Ab + (size_t)(b0 + lrow) * HN;
    const float* bRow = Wfc + (size_t)lrow * (2 * HN);

    float acc[4][4][4];
#pragma unroll
    for (int i = 0; i < 4; i++)
#pragma unroll
        for (int jx = 0; jx < 4; jx++)
#pragma unroll
            for (int kx = 0; kx < 4; kx++) acc[i][jx][kx] = 0.f;

    float4 ra0, ra1, rb0, rb1;

#define LOAD_CHUNK_FC(kc)                                                   \
    {                                                                       \
        int k = (kc) * KC + lhalf * 8;                                      \
        const float* srcA = (k < 512) ? (afRow + k) : (abRow + (k - 512));  \
        ra0 = cvt4(*(const float4*)(srcA));                                 \
        ra1 = cvt4(*(const float4*)(srcA + 4));                             \
        rb0 = cvt4(*(const float4*)(bRow + k));                             \
        rb1 = cvt4(*(const float4*)(bRow + k + 4));                         \
    }

    LOAD_CHUNK_FC(0);
    sts_chunk(As, Bs, lrow, lhalf, ra0, ra1, rb0, rb1);
    __syncthreads();

    const int NK = 1024 / KC;  // 64
    for (int kc = 0; kc < NK; kc++) {
        bool more = (kc + 1 < NK);
        if (more) LOAD_CHUNK_FC(kc + 1);
        compute_chunk(As, Bs, wm, wn, gr, q, acc);
        __syncthreads();
        if (more) {
            sts_chunk(As, Bs, lrow, lhalf, ra0, ra1, rb0, rb1);
            __syncthreads();
        }
    }
#undef LOAD_CHUNK_FC

#pragma unroll
    for (int tm = 0; tm < 4; tm++) {
        int b = b0 + wm * 64 + tm * 16 + gr;
#pragma unroll
        for (int tn = 0; tn < 4; tn++) {
            int n0 = wn * 32 + tn * 8 + 2 * q;
            float2 w0 = make_float2(acc[tm][tn][0] + bsh[n0], acc[tm][tn][1] + bsh[n0 + 1]);
            *(float2*)(y + ((size_t)b * SN + s) * VN + n0) = w0;
            float2 w1 = make_float2(acc[tm][tn][2] + bsh[n0], acc[tm][tn][3] + bsh[n0 + 1]);
            *(float2*)(y + ((size_t)(b + 8) * SN + s) * VN + n0) = w1;
        }
    }
}

extern "C" void kernel_launch(void* const* d_in, const int* in_sizes, int n_in,
                              void* d_out, int out_size) {
    const int*   x    = (const int*)d_in[0];
    const float* Wx_f = (const float*)d_in[1];
    const float* Wh_f = (const float*)d_in[2];
    const float* bx_f = (const float*)d_in[3];
    const float* bh_f = (const float*)d_in[4];
    const float* Wx_b = (const float*)d_in[5];
    const float* Wh_b = (const float*)d_in[6];
    const float* bx_b = (const float*)d_in[7];
    const float* bh_b = (const float*)d_in[8];
    const float* Wfc  = (const float*)d_in[9];
    const float* bfc  = (const float*)d_in[10];
    float* y = (float*)d_out;

    // zero h0 / c0 state
    init_kernel<<<2048, 256>>>();

    // 256 sequential recurrence steps; both directions fused per launch.
    dim3 g(4, 16, 2);  // 4 batch tiles x 16 neuron tiles x 2 directions = 128 CTAs
    for (int t = 0; t < SN; t++)
        step_kernel<<<g, 256>>>(t, x, Wx_f, Wh_f, bx_f, bh_f, Wx_b, Wh_b, bx_b, bh_b);

    // final projection over all (s, b)
    fc_kernel<<<1024, 256>>>(Wfc, bfc, y);
}

// round 9
// speedup vs baseline: 1.2774x; 1.2774x over previous
#include <cuda_runtime.h>
#include <cstdint>
#include <cstddef>

// Problem dims
#define VN 128
#define HN 512
#define BN 512
#define SN 256
#define KC 16   // K-chunk per smem stage

// Static scratch (module-load allocated; no runtime allocation)
__device__ float g_hs_f[(size_t)(SN + 1) * BN * HN];  // forward h history (tf32-rounded values)
__device__ float g_hs_b[(size_t)(SN + 1) * BN * HN];  // backward-scan h history
__device__ float g_c[2 * BN * HN];                    // cell state (f32), [dir][b][j]
// Pre-packed tf32 weights: [dir][n = j*4+gate][k], k<512 -> Wh, k>=512 -> Wx
__device__ float g_w[(size_t)2 * 2048 * 640];

__device__ __forceinline__ float to_tf32(float x) {
    float r;
    asm("cvt.rna.tf32.f32 %0, %1;" : "=f"(r) : "f"(x));
    return r;
}

__device__ __forceinline__ float4 cvt4(float4 v) {
    return make_float4(to_tf32(v.x), to_tf32(v.y), to_tf32(v.z), to_tf32(v.w));
}

__device__ __forceinline__ void mma_tf32(float* d, const unsigned* a, const unsigned* b) {
    asm volatile(
        "mma.sync.aligned.m16n8k8.row.col.f32.tf32.tf32.f32 "
        "{%0,%1,%2,%3}, {%4,%5,%6,%7}, {%8,%9}, {%0,%1,%2,%3};\n"
        : "+f"(d[0]), "+f"(d[1]), "+f"(d[2]), "+f"(d[3])
        : "r"(a[0]), "r"(a[1]), "r"(a[2]), "r"(a[3]),
          "r"(b[0]), "r"(b[1]));
}

__device__ __forceinline__ float sigmf(float x) { return 1.0f / (1.0f + expf(-x)); }

// ---------- compute over one staged KC=16 chunk, warp tile 32x32 (16-warp CTA) ----------
__device__ __forceinline__ void compute_chunk2(const float* As, const float* Bs,
                                               int wm, int wn, int gr, int q,
                                               float acc[2][4][4]) {
#pragma unroll
    for (int ks = 0; ks < 2; ks++) {
        const int kk = ks * 8;
        unsigned af[2][4], bf[4][2];
#pragma unroll
        for (int tm = 0; tm < 2; tm++) {
            int r = wm * 32 + tm * 16 + gr;
            int c = kk + q;
            af[tm][0] = __float_as_uint(As[r * 20 + c]);
            af[tm][1] = __float_as_uint(As[(r + 8) * 20 + c]);
            af[tm][2] = __float_as_uint(As[r * 20 + c + 4]);
            af[tm][3] = __float_as_uint(As[(r + 8) * 20 + c + 4]);
        }
#pragma unroll
        for (int tn = 0; tn < 4; tn++) {
            int n = wn * 32 + tn * 8 + gr;
            bf[tn][0] = __float_as_uint(Bs[n * 20 + kk + q]);
            bf[tn][1] = __float_as_uint(Bs[n * 20 + kk + q + 4]);
        }
#pragma unroll
        for (int tm = 0; tm < 2; tm++)
#pragma unroll
            for (int tn = 0; tn < 4; tn++)
                mma_tf32(acc[tm][tn], af[tm], bf[tn]);
    }
}

// ---------- compute over one staged KC=16 chunk, warp tile 64x32 (8-warp CTA, FC) ----------
__device__ __forceinline__ void compute_chunk4(const float* As, const float* Bs,
                                               int wm, int wn, int gr, int q,
                                               float acc[4][4][4]) {
#pragma unroll
    for (int ks = 0; ks < 2; ks++) {
        const int kk = ks * 8;
        unsigned af[4][4], bf[4][2];
#pragma unroll
        for (int tm = 0; tm < 4; tm++) {
            int r = wm * 64 + tm * 16 + gr;
            int c = kk + q;
            af[tm][0] = __float_as_uint(As[r * 20 + c]);
            af[tm][1] = __float_as_uint(As[(r + 8) * 20 + c]);
            af[tm][2] = __float_as_uint(As[r * 20 + c + 4]);
            af[tm][3] = __float_as_uint(As[(r + 8) * 20 + c + 4]);
        }
#pragma unroll
        for (int tn = 0; tn < 4; tn++) {
            int n = wn * 32 + tn * 8 + gr;
            bf[tn][0] = __float_as_uint(Bs[n * 20 + kk + q]);
            bf[tn][1] = __float_as_uint(Bs[n * 20 + kk + q + 4]);
        }
#pragma unroll
        for (int tm = 0; tm < 4; tm++)
#pragma unroll
            for (int tn = 0; tn < 4; tn++)
                mma_tf32(acc[tm][tn], af[tm], bf[tn]);
    }
}

__global__ void init_kernel() {
    int i = blockIdx.x * blockDim.x + threadIdx.x;
    if (i < BN * HN) { g_hs_f[i] = 0.f; g_hs_b[i] = 0.f; }
    if (i < 2 * BN * HN) g_c[i] = 0.f;
}

// Pre-pack [Wh | Wx] into tf32, B-row order n = j*4 + gate, contiguous k.
__global__ void pack_w_kernel(const float* __restrict__ Wh_f, const float* __restrict__ Wx_f,
                              const float* __restrict__ Wh_b, const float* __restrict__ Wx_b) {
    size_t i = (size_t)blockIdx.x * blockDim.x + threadIdx.x;
    const size_t total = (size_t)2 * 2048 * 640;
    if (i >= total) return;
    int k = (int)(i % 640);
    int n = (int)((i / 640) % 2048);
    int d = (int)(i / ((size_t)640 * 2048));
    int j = n >> 2, gate = n & 3;
    const float* Wh = d ? Wh_b : Wh_f;
    const float* Wx = d ? Wx_b : Wx_f;
    float v = (k < 512) ? Wh[((size_t)gate * HN + j) * HN + k]
                        : Wx[((size_t)gate * HN + j) * VN + (k - 512)];
    g_w[i] = to_tf32(v);
}

// One recurrence step, both directions (blockIdx.z). 512 threads = 16 warps (4x4),
// CTA tile 128 batch rows x 32 neurons (128 GEMM cols), K = 640 (512 h_prev + 128 one-hot).
// Double-buffered smem, one __syncthreads per KC=16 chunk, LDG prefetch one chunk ahead.
__global__ __launch_bounds__(512) void step_kernel(
    int t, const int* __restrict__ x,
    const float* __restrict__ bx_f, const float* __restrict__ bh_f,
    const float* __restrict__ bx_b, const float* __restrict__ bh_b) {
    __shared__ __align__(16) float As[2][128 * 20];
    __shared__ __align__(16) float Bs[2][128 * 20];
    __shared__ float bsum[128];

    const int tid = threadIdx.x;
    const int d = blockIdx.z;
    const int b0 = blockIdx.x * 128;
    const int j0 = blockIdx.y * 32;
    const int t_eff = d ? (SN - 1 - t) : t;

    const float* __restrict__ bxp = d ? bx_b : bx_f;
    const float* __restrict__ bhp = d ? bh_b : bh_f;
    float* hs = d ? g_hs_b : g_hs_f;
    float* cst = g_c + (size_t)d * BN * HN;
    const float* hprev = hs + (size_t)t * BN * HN;
    float* hout = hs + (size_t)(t + 1) * BN * HN;

    if (tid < 128) {
        int jj = tid >> 2, gate = tid & 3, j = j0 + jj;
        bsum[tid] = bxp[gate * HN + j] + bhp[gate * HN + j];
    }

    // loader mapping: each thread owns one float4 of A and one of B per chunk
    const int lrow = tid >> 2;   // 0..127
    const int lseg = tid & 3;    // 0..3 (16-float chunk = 4 float4 segments)
    const int warp = tid >> 5, lane = tid & 31;
    const int wm = warp >> 2, wn = warp & 3;   // 4x4 warp grid, warp tile 32x32
    const int gr = lane >> 2, q = lane & 3;

    const float* aRow = hprev + (size_t)(b0 + lrow) * HN;                      // tf32 values
    const float* bRow = g_w + ((size_t)d * 2048 + (size_t)j0 * 4 + lrow) * 640; // tf32 packed
    const int xv = x[(b0 + lrow) * SN + t_eff];

    float acc[2][4][4];
#pragma unroll
    for (int i = 0; i < 2; i++)
#pragma unroll
        for (int jx = 0; jx < 4; jx++)
#pragma unroll
            for (int kx = 0; kx < 4; kx++) acc[i][jx][kx] = 0.f;

    float4 rA[2], rB[2];

#define LOADC(kc, ra, rb)                                                            \
    {                                                                                \
        int k = (kc) * KC + lseg * 4;                                                \
        if (k < 512) {                                                               \
            ra = *(const float4*)(aRow + k);                                         \
        } else {                                                                     \
            int kk = k - 512;                                                        \
            ra = make_float4(xv == kk + 0 ? 1.f : 0.f, xv == kk + 1 ? 1.f : 0.f,     \
                             xv == kk + 2 ? 1.f : 0.f, xv == kk + 3 ? 1.f : 0.f);    \
        }                                                                            \
        rb = *(const float4*)(bRow + k);                                             \
    }

    LOADC(0, rA[0], rB[0]);

    const int NK = 640 / KC;  // 40
#pragma unroll 2
    for (int kc = 0; kc < NK; kc++) {
        const int p = kc & 1;
        *(float4*)(As[p] + lrow * 20 + lseg * 4) = rA[p];
        *(float4*)(Bs[p] + lrow * 20 + lseg * 4) = rB[p];
        if (kc + 1 < NK) LOADC(kc + 1, rA[p ^ 1], rB[p ^ 1]);
        __syncthreads();
        compute_chunk2(As[p], Bs[p], wm, wn, gr, q, acc);
    }
#undef LOADC

    // --- epilogue: gates + cell update. Lane pair (l, l^1) exchanges to gather all 4 gates. ---
#pragma unroll
    for (int tm = 0; tm < 2; tm++) {
        int rbase = b0 + wm * 32 + tm * 16 + gr;
#pragma unroll
        for (int tn = 0; tn < 4; tn++) {
            float c0 = acc[tm][tn][0], c1 = acc[tm][tn][1];
            float c2 = acc[tm][tn][2], c3 = acc[tm][tn][3];
            float e0 = __shfl_xor_sync(0xffffffffu, c0, 1);
            float e1 = __shfl_xor_sync(0xffffffffu, c1, 1);
            float e2 = __shfl_xor_sync(0xffffffffu, c2, 1);
            float e3 = __shfl_xor_sync(0xffffffffu, c3, 1);
            float iv, fv, ov, gv;
            int brow;
            if ((q & 1) == 0) { iv = c0; fv = c1; ov = e0; gv = e1; brow = rbase; }
            else              { iv = e2; fv = e3; ov = c2; gv = c3; brow = rbase + 8; }
            int jj4 = wn * 32 + tn * 8 + (q >> 1) * 4;
            float4 bs = *(const float4*)&bsum[jj4];
            float gi = sigmf(iv + bs.x);
            float gf = sigmf(fv + bs.y);
            float go = sigmf(ov + bs.z);
            float gg = tanhf(gv + bs.w);
            size_t ci = (size_t)brow * HN + (size_t)(j0 + (jj4 >> 2));
            float cn = gf * cst[ci] + gi * gg;
            cst[ci] = cn;
            hout[ci] = to_tf32(go * tanhf(cn));  // pre-round: MMA consumers need no cvt
        }
    }
}

// Final FC: y[b,s,v] = [hf(s) | hb(s)] . Wfc[v,:] + bfc[v].  M = S*B, N = V = 128, K = 1024.
__global__ __launch_bounds__(256) void fc_kernel(const float* __restrict__ Wfc,
                                                 const float* __restrict__ bfc,
                                                 float* __restrict__ y) {
    __shared__ __align__(16) float As[128 * 20];
    __shared__ __align__(16) float Bs[128 * 20];
    __shared__ float bsh[128];

    const int tid = threadIdx.x;
    const int mt = blockIdx.x;       // 1024 CTAs: 256 s values x 4 batch tiles
    const int s = mt >> 2;
    const int b0 = (mt & 3) * 128;

    const float* Af = g_hs_f + (size_t)(s + 1) * BN * HN;   // hf[s]
    const float* Ab = g_hs_b + (size_t)(SN - s) * BN * HN;  // hb[s] (un-reversed)

    if (tid < 128) bsh[tid] = bfc[tid];

    const int lrow = tid >> 1, lhalf = tid & 1;
    const int warp = tid >> 5, lane = tid & 31;
    const int wm = warp >> 2, wn = warp & 3;
    const int gr = lane >> 2, q = lane & 3;

    const float* afRow = Af + (size_t)(b0 + lrow) * HN;
    const float* abRow = Ab + (size_t)(b0 + lrow) * HN;
    const float* bRow = Wfc + (size_t)lrow * (2 * HN);

    float acc[4][4][4];
#pragma unroll
    for (int i = 0; i < 4; i++)
#pragma unroll
        for (int jx = 0; jx < 4; jx++)
#pragma unroll
            for (int kx = 0; kx < 4; kx++) acc[i][jx][kx] = 0.f;

    float4 ra0, ra1, rb0, rb1;

#define LOAD_CHUNK_FC(kc)                                                   \
    {                                                                       \
        int k = (kc) * KC + lhalf * 8;                                      \
        const float* srcA = (k < 512) ? (afRow + k) : (abRow + (k - 512));  \
        ra0 = *(const float4*)(srcA);                                       \
        ra1 = *(const float4*)(srcA + 4);                                   \
        rb0 = cvt4(*(const float4*)(bRow + k));                             \
        rb1 = cvt4(*(const float4*)(bRow + k + 4));                        \
    }

    LOAD_CHUNK_FC(0);
    {
        *(float4*)(As + lrow * 20 + lhalf * 8)     = ra0;
        *(float4*)(As + lrow * 20 + lhalf * 8 + 4) = ra1;
        *(float4*)(Bs + lrow * 20 + lhalf * 8)     = rb0;
        *(float4*)(Bs + lrow * 20 + lhalf * 8 + 4) = rb1;
    }
    __syncthreads();

    const int NK = 1024 / KC;  // 64
    for (int kc = 0; kc < NK; kc++) {
        bool more = (kc + 1 < NK);
        if (more) LOAD_CHUNK_FC(kc + 1);
        compute_chunk4(As, Bs, wm, wn, gr, q, acc);
        __syncthreads();
        if (more) {
            *(float4*)(As + lrow * 20 + lhalf * 8)     = ra0;
            *(float4*)(As + lrow * 20 + lhalf * 8 + 4) = ra1;
            *(float4*)(Bs + lrow * 20 + lhalf * 8)     = rb0;
            *(float4*)(Bs + lrow * 20 + lhalf * 8 + 4) = rb1;
            __syncthreads();
        }
    }
#undef LOAD_CHUNK_FC

#pragma unroll
    for (int tm = 0; tm < 4; tm++) {
        int b = b0 + wm * 64 + tm * 16 + gr;
#pragma unroll
        for (int tn = 0; tn < 4; tn++) {
            int n0 = wn * 32 + tn * 8 + 2 * q;
            float2 w0 = make_float2(acc[tm][tn][0] + bsh[n0], acc[tm][tn][1] + bsh[n0 + 1]);
            *(float2*)(y + ((size_t)b * SN + s) * VN + n0) = w0;
            float2 w1 = make_float2(acc[tm][tn][2] + bsh[n0], acc[tm][tn][3] + bsh[n0 + 1]);
            *(float2*)(y + ((size_t)(b + 8) * SN + s) * VN + n0) = w1;
        }
    }
}

extern "C" void kernel_launch(void* const* d_in, const int* in_sizes, int n_in,
                              void* d_out, int out_size) {
    const int*   x    = (const int*)d_in[0];
    const float* Wx_f = (const float*)d_in[1];
    const float* Wh_f = (const float*)d_in[2];
    const float* bx_f = (const float*)d_in[3];
    const float* bh_f = (const float*)d_in[4];
    const float* Wx_b = (const float*)d_in[5];
    const float* Wh_b = (const float*)d_in[6];
    const float* bx_b = (const float*)d_in[7];
    const float* bh_b = (const float*)d_in[8];
    const float* Wfc  = (const float*)d_in[9];
    const float* bfc  = (const float*)d_in[10];
    float* y = (float*)d_out;

    // zero h0 / c0 state + pre-pack tf32 weights (runs every replay; ~tens of us)
    init_kernel<<<2048, 256>>>();
    pack_w_kernel<<<(2 * 2048 * 640 + 255) / 256, 256>>>(Wh_f, Wx_f, Wh_b, Wx_b);

    // 256 sequential recurrence steps; both directions fused per launch.
    dim3 g(4, 16, 2);  // 4 batch tiles x 16 neuron tiles x 2 directions = 128 CTAs
    for (int t = 0; t < SN; t++)
        step_kernel<<<g, 512>>>(t, x, bx_f, bh_f, bx_b, bh_b);

    // final projection over all (s, b)
    fc_kernel<<<1024, 256>>>(Wfc, bfc, y);
}

// round 10
// speedup vs baseline: 1.3804x; 1.0806x over previous
#include <cuda_runtime.h>
#include <cstdint>
#include <cstddef>

// Problem dims
#define VN 128
#define HN 512
#define BN 512
#define SN 256

// Static scratch (module-load allocated; no runtime allocation)
// h is stored tf32-rounded AND perm16-permuted within each 16-k chunk.
__device__ float g_hs_f[(size_t)(SN + 1) * BN * HN];
__device__ float g_hs_b[(size_t)(SN + 1) * BN * HN];
__device__ float g_c[2 * BN * HN];                     // cell state (plain layout)
// Pre-packed tf32 weights, perm16'd k: [dir][n = j*4+gate][k'], k<512 Wh, k>=512 Wx
__device__ float g_w[(size_t)2 * 2048 * 640];
__device__ float g_wfc[(size_t)VN * 1024];             // perm16'd [v][k']

__device__ __forceinline__ float to_tf32(float x) {
    float r;
    asm("cvt.rna.tf32.f32 %0, %1;" : "=f"(r) : "f"(x));
    return r;
}

__device__ __host__ __forceinline__ int perm16(int c) { return (c & 3) * 4 + (c >> 2); }

__device__ __forceinline__ void mma_tf32(float* d, const unsigned* a, const unsigned* b) {
    asm volatile(
        "mma.sync.aligned.m16n8k8.row.col.f32.tf32.tf32.f32 "
        "{%0,%1,%2,%3}, {%4,%5,%6,%7}, {%8,%9}, {%0,%1,%2,%3};\n"
        : "+f"(d[0]), "+f"(d[1]), "+f"(d[2]), "+f"(d[3])
        : "r"(a[0]), "r"(a[1]), "r"(a[2]), "r"(a[3]),
          "r"(b[0]), "r"(b[1]));
}

__device__ __forceinline__ float sigmf(float x) { return 1.0f / (1.0f + expf(-x)); }

__global__ void init_kernel() {
    int i = blockIdx.x * blockDim.x + threadIdx.x;
    if (i < BN * HN) { g_hs_f[i] = 0.f; g_hs_b[i] = 0.f; }
    if (i < 2 * BN * HN) g_c[i] = 0.f;
}

// Pack [Wh | Wx] -> tf32, n = j*4+gate, k' = perm16 within 16-chunks.
__global__ void pack_w_kernel(const float* __restrict__ Wh_f, const float* __restrict__ Wx_f,
                              const float* __restrict__ Wh_b, const float* __restrict__ Wx_b) {
    size_t i = (size_t)blockIdx.x * blockDim.x + threadIdx.x;
    const size_t total = (size_t)2 * 2048 * 640;
    if (i >= total) return;
    int kp = (int)(i % 640);
    int n = (int)((i / 640) % 2048);
    int d = (int)(i / ((size_t)640 * 2048));
    int k = (kp & ~15) + perm16(kp & 15);   // perm16 is an involution
    int j = n >> 2, gate = n & 3;
    const float* Wh = d ? Wh_b : Wh_f;
    const float* Wx = d ? Wx_b : Wx_f;
    float v = (k < 512) ? Wh[((size_t)gate * HN + j) * HN + k]
                        : Wx[((size_t)gate * HN + j) * VN + (k - 512)];
    g_w[i] = to_tf32(v);
}

__global__ void pack_wfc_kernel(const float* __restrict__ Wfc) {
    int i = blockIdx.x * blockDim.x + threadIdx.x;
    if (i >= VN * 1024) return;
    int kp = i & 1023, v = i >> 10;
    int k = (kp & ~15) + perm16(kp & 15);
    g_wfc[i] = to_tf32(Wfc[v * 1024 + k]);
}

// ============================================================================
// step_kernel: one recurrence step, both directions (blockIdx.z).
// CTA tile 64 batch x 256 gemm cols (64 neurons x 4 gates), K=640.
// 8 warps, 1x8 column split, warp tile 64x32.
// A (h_prev) via smem, perm16 layout + row-swizzle -> LDS.128 fragments.
// B (weights) direct from L2 as LDG.128 fragments (pre-permuted g_w).
// ============================================================================
__global__ __launch_bounds__(256) void step_kernel(
    int t, const int* __restrict__ x,
    const float* __restrict__ bx_f, const float* __restrict__ bh_f,
    const float* __restrict__ bx_b, const float* __restrict__ bh_b) {
    __shared__ __align__(16) float As[2][64 * 16];
    __shared__ __align__(16) float bsum[256];

    const int tid = threadIdx.x;
    const int d = blockIdx.z;
    const int b0 = blockIdx.x * 64;
    const int j0 = blockIdx.y * 64;   // first neuron of this CTA
    const int t_eff = d ? (SN - 1 - t) : t;

    const float* __restrict__ bxp = d ? bx_b : bx_f;
    const float* __restrict__ bhp = d ? bh_b : bh_f;
    float* hs = d ? g_hs_b : g_hs_f;
    float* cst = g_c + (size_t)d * BN * HN;
    const float* hprev = hs + (size_t)t * BN * HN;
    float* hout = hs + (size_t)(t + 1) * BN * HN;

    {   // per-col bias sums (col n = jj*4+gate)
        int jj = tid >> 2, gate = tid & 3, j = j0 + jj;
        bsum[tid] = bxp[gate * HN + j] + bhp[gate * HN + j];
    }

    const int lrow = tid >> 2, lseg = tid & 3;       // A loader: 1 float4/thread
    const int w = tid >> 5, lane = tid & 31;
    const int gr = lane >> 2, q = lane & 3;
    const int swz = (gr >> 1) & 3;
    const int stsOff = lrow * 16 + 4 * (lseg ^ ((lrow >> 1) & 3));
    const int aBase0 = gr * 16 + 4 * (q ^ swz);      // frag addr, row gr

    const float* aRow = hprev + (size_t)(b0 + lrow) * HN;   // perm'd tf32
    const int xv = x[(b0 + lrow) * SN + t_eff];
    const float* bPtr = g_w + ((size_t)d * 2048 + (size_t)j0 * 4 + w * 32 + gr) * 640 + 4 * q;

    float acc[4][4][4];
#pragma unroll
    for (int i = 0; i < 4; i++)
#pragma unroll
        for (int jx = 0; jx < 4; jx++)
#pragma unroll
            for (int kx = 0; kx < 4; kx++) acc[i][jx][kx] = 0.f;

    float4 bF[2][4], rA;

#define LOADA(ch, dst)                                                                \
    {                                                                                 \
        if ((ch) < 32) {                                                              \
            dst = *(const float4*)(aRow + (ch) * 16 + lseg * 4);                      \
        } else {                                                                      \
            int kb = ((ch) - 32) * 16 + lseg; /* component j -> vocab kb + 4j */      \
            dst = make_float4(xv == kb ? 1.f : 0.f, xv == kb + 4 ? 1.f : 0.f,         \
                              xv == kb + 8 ? 1.f : 0.f, xv == kb + 12 ? 1.f : 0.f);   \
        }                                                                             \
    }
#define LOADB(ch, buf)                                                                \
    {                                                                                 \
        _Pragma("unroll")                                                             \
        for (int tn = 0; tn < 4; tn++)                                                \
            bF[buf][tn] = *(const float4*)(bPtr + (size_t)tn * 8 * 640 + (ch) * 16);  \
    }
#define COMPUTE(p, bb)                                                                \
    {                                                                                 \
        const float* S = As[p];                                                       \
        float4 a0[4], a1[4];                                                          \
        _Pragma("unroll")                                                             \
        for (int tm = 0; tm < 4; tm++) {                                              \
            a0[tm] = *(const float4*)(S + tm * 256 + aBase0);                         \
            a1[tm] = *(const float4*)(S + tm * 256 + aBase0 + 128);                   \
        }                                                                             \
        _Pragma("unroll")                                                             \
        for (int tm = 0; tm < 4; tm++) {                                              \
            unsigned af0[4] = {__float_as_uint(a0[tm].x), __float_as_uint(a1[tm].x),  \
                               __float_as_uint(a0[tm].y), __float_as_uint(a1[tm].y)}; \
            unsigned af1[4] = {__float_as_uint(a0[tm].z), __float_as_uint(a1[tm].z),  \
                               __float_as_uint(a0[tm].w), __float_as_uint(a1[tm].w)}; \
            _Pragma("unroll")                                                         \
            for (int tn = 0; tn < 4; tn++) {                                          \
                unsigned bk0[2] = {__float_as_uint(bF[bb][tn].x),                     \
                                   __float_as_uint(bF[bb][tn].y)};                    \
                unsigned bk1[2] = {__float_as_uint(bF[bb][tn].z),                     \
                                   __float_as_uint(bF[bb][tn].w)};                    \
                mma_tf32(acc[tm][tn], af0, bk0);                                      \
                mma_tf32(acc[tm][tn], af1, bk1);                                      \
            }                                                                         \
        }                                                                             \
    }

    LOADA(0, rA);
    LOADB(0, 0);
    for (int kc = 0; kc < 40; kc += 2) {
        // phase 0: chunk kc
        *(float4*)(&As[0][stsOff]) = rA;
        LOADA(kc + 1, rA);
        LOADB(kc + 1, 1);
        __syncthreads();
        COMPUTE(0, 0);
        // phase 1: chunk kc+1
        *(float4*)(&As[1][stsOff]) = rA;
        if (kc + 2 < 40) { LOADA(kc + 2, rA); LOADB(kc + 2, 0); }
        __syncthreads();
        COMPUTE(1, 1);
    }
#undef LOADA
#undef LOADB
#undef COMPUTE

    // Epilogue: lane pair (l, l^1) exchanges to gather all 4 gates of a cell.
#pragma unroll
    for (int tm = 0; tm < 4; tm++) {
        int rbase = b0 + tm * 16 + gr;
#pragma unroll
        for (int tn = 0; tn < 4; tn++) {
            float c0 = acc[tm][tn][0], c1 = acc[tm][tn][1];
            float c2 = acc[tm][tn][2], c3 = acc[tm][tn][3];
            float e0 = __shfl_xor_sync(0xffffffffu, c0, 1);
            float e1 = __shfl_xor_sync(0xffffffffu, c1, 1);
            float e2 = __shfl_xor_sync(0xffffffffu, c2, 1);
            float e3 = __shfl_xor_sync(0xffffffffu, c3, 1);
            float iv, fv, ov, gv;
            int brow;
            if ((q & 1) == 0) { iv = c0; fv = c1; ov = e0; gv = e1; brow = rbase; }
            else              { iv = e2; fv = e3; ov = c2; gv = c3; brow = rbase + 8; }
            int jj4 = w * 32 + tn * 8 + (q >> 1) * 4;
            float4 bs = *(const float4*)&bsum[jj4];
            float gi = sigmf(iv + bs.x);
            float gf = sigmf(fv + bs.y);
            float go = sigmf(ov + bs.z);
            float gg = tanhf(gv + bs.w);
            int jg = j0 + (jj4 >> 2);
            int kp = (jg & ~15) | perm16(jg & 15);   // store h permuted
            size_t ci = (size_t)brow * HN + jg;
            float cn = gf * cst[ci] + gi * gg;
            cst[ci] = cn;
            hout[(size_t)brow * HN + kp] = to_tf32(go * tanhf(cn));
        }
    }
}

// ============================================================================
// fc_kernel: y[b,s,v] = [hf(s)|hb(s)] . Wfc[v,:] + bfc[v]. K=1024, 64 chunks.
// CTA 128 rows x 128 cols, 8 warps 2x4, warp tile 64x32. A and B via smem
// with perm16 + swizzle (both stored pre-permuted in global).
// ============================================================================
__global__ __launch_bounds__(256) void fc_kernel(const float* __restrict__ bfc,
                                                 float* __restrict__ y) {
    __shared__ __align__(16) float As[2][128 * 16];
    __shared__ __align__(16) float Bs[2][128 * 16];
    __shared__ float bsh[128];

    const int tid = threadIdx.x;
    const int s = blockIdx.x >> 2;
    const int b0r = (blockIdx.x & 3) * 128;

    const float* Af = g_hs_f + (size_t)(s + 1) * BN * HN;
    const float* Ab = g_hs_b + (size_t)(SN - s) * BN * HN;

    if (tid < 128) bsh[tid] = bfc[tid];

    const int lrow = tid >> 1;              // loader: 2 float4 per thread
    const int sb = (tid & 1) * 2;           // seg base
    const int lswz = (lrow >> 1) & 3;
    const int o0 = lrow * 16 + 4 * (sb ^ lswz);
    const int o1 = lrow * 16 + 4 * ((sb + 1) ^ lswz);

    const int warp = tid >> 5, lane = tid & 31;
    const int wm = warp >> 2, wn = warp & 3;
    const int gr = lane >> 2, q = lane & 3;
    const int swz = (gr >> 1) & 3;
    const int aBase0 = gr * 16 + 4 * (q ^ swz);

    const float* afRow = Af + (size_t)(b0r + lrow) * HN;
    const float* abRow = Ab + (size_t)(b0r + lrow) * HN;
    const float* bRow = g_wfc + (size_t)lrow * 1024;

    float acc[4][4][4];
#pragma unroll
    for (int i = 0; i < 4; i++)
#pragma unroll
        for (int jx = 0; jx < 4; jx++)
#pragma unroll
            for (int kx = 0; kx < 4; kx++) acc[i][jx][kx] = 0.f;

    float4 rA0, rA1, rB0, rB1;

#define LOADFC(ch)                                                              \
    {                                                                           \
        int kp = (ch) * 16 + sb * 4;                                            \
        const float* srcA = (kp < 512) ? (afRow + kp) : (abRow + (kp - 512));   \
        rA0 = *(const float4*)(srcA);                                           \
        rA1 = *(const float4*)(srcA + 4);                                       \
        rB0 = *(const float4*)(bRow + kp);                                      \
        rB1 = *(const float4*)(bRow + kp + 4);                                  \
    }
#define STORFC(p)                                                               \
    {                                                                           \
        *(float4*)(&As[p][o0]) = rA0;                                           \
        *(float4*)(&As[p][o1]) = rA1;                                           \
        *(float4*)(&Bs[p][o0]) = rB0;                                           \
        *(float4*)(&Bs[p][o1]) = rB1;                                           \
    }
#define COMPFC(p)                                                               \
    {                                                                           \
        const float* SA = As[p];                                                \
        const float* SB = Bs[p];                                                \
        float4 a0[4], a1[4], bq[4];                                             \
        _Pragma("unroll")                                                       \
        for (int tm = 0; tm < 4; tm++) {                                        \
            a0[tm] = *(const float4*)(SA + wm * 1024 + tm * 256 + aBase0);      \
            a1[tm] = *(const float4*)(SA + wm * 1024 + tm * 256 + aBase0 + 128);\
        }                                                                       \
        _Pragma("unroll")                                                       \
        for (int tn = 0; tn < 4; tn++)                                          \
            bq[tn] = *(const float4*)(SB + wn * 512 + tn * 128 + aBase0);       \
        _Pragma("unroll")                                                       \
        for (int tm = 0; tm < 4; tm++) {                                        \
            unsigned af0[4] = {__float_as_uint(a0[tm].x), __float_as_uint(a1[tm].x),\
                               __float_as_uint(a0[tm].y), __float_as_uint(a1[tm].y)};\
            unsigned af1[4] = {__float_as_uint(a0[tm].z), __float_as_uint(a1[tm].z),\
                               __float_as_uint(a0[tm].w), __float_as_uint(a1[tm].w)};\
            _Pragma("unroll")                                                   \
            for (int tn = 0; tn < 4; tn++) {                                    \
                unsigned bk0[2] = {__float_as_uint(bq[tn].x), __float_as_uint(bq[tn].y)};\
                unsigned bk1[2] = {__float_as_uint(bq[tn].z), __float_as_uint(bq[tn].w)};\
                mma_tf32(acc[tm][tn], af0, bk0);                                \
                mma_tf32(acc[tm][tn], af1, bk1);                                \
            }                                                                   \
        }                                                                       \
    }

    LOADFC(0);
    for (int kc = 0; kc < 64; kc += 2) {
        STORFC(0);
        LOADFC(kc + 1);
        __syncthreads();
        COMPFC(0);
        STORFC(1);
        if (kc + 2 < 64) LOADFC(kc + 2);
        __syncthreads();
        COMPFC(1);
    }
#undef LOADFC
#undef STORFC
#undef COMPFC

#pragma unroll
    for (int tm = 0; tm < 4; tm++) {
        int b = b0r + wm * 64 + tm * 16 + gr;
#pragma unroll
        for (int tn = 0; tn < 4; tn++) {
            int n0 = wn * 32 + tn * 8 + 2 * q;
            float2 w0 = make_float2(acc[tm][tn][0] + bsh[n0], acc[tm][tn][1] + bsh[n0 + 1]);
            *(float2*)(y + ((size_t)b * SN + s) * VN + n0) = w0;
            float2 w1 = make_float2(acc[tm][tn][2] + bsh[n0], acc[tm][tn][3] + bsh[n0 + 1]);
            *(float2*)(y + ((size_t)(b + 8) * SN + s) * VN + n0) = w1;
        }
    }
}

extern "C" void kernel_launch(void* const* d_in, const int* in_sizes, int n_in,
                              void* d_out, int out_size) {
    const int*   x    = (const int*)d_in[0];
    const float* Wx_f = (const float*)d_in[1];
    const float* Wh_f = (const float*)d_in[2];
    const float* bx_f = (const float*)d_in[3];
    const float* bh_f = (const float*)d_in[4];
    const float* Wx_b = (const float*)d_in[5];
    const float* Wh_b = (const float*)d_in[6];
    const float* bx_b = (const float*)d_in[7];
    const float* bh_b = (const float*)d_in[8];
    const float* Wfc  = (const float*)d_in[9];
    const float* bfc  = (const float*)d_in[10];
    float* y = (float*)d_out;

    init_kernel<<<2048, 256>>>();
    pack_w_kernel<<<(2 * 2048 * 640 + 255) / 256, 256>>>(Wh_f, Wx_f, Wh_b, Wx_b);
    pack_wfc_kernel<<<(VN * 1024 + 255) / 256, 256>>>(Wfc);

    // 256 sequential recurrence steps; both directions fused per launch.
    dim3 g(8, 8, 2);  // 8 batch tiles x 8 neuron tiles x 2 directions = 128 CTAs
    for (int t = 0; t < SN; t++)
        step_kernel<<<g, 256>>>(t, x, bx_f, bh_f, bx_b, bh_b);

    // final projection over all (s, b)
    fc_kernel<<<1024, 256>>>(bfc, y);
}

// round 11
// speedup vs baseline: 1.4621x; 1.0592x over previous
#include <cuda_runtime.h>
#include <cstdint>
#include <cstddef>

// Problem dims
#define VN 128
#define HN 512
#define BN 512
#define SN 256

// Static scratch (module-load allocated; no runtime allocation)
// h is stored tf32-rounded AND perm16-permuted within each 16-k chunk.
__device__ float g_hs_f[(size_t)(SN + 1) * BN * HN];
__device__ float g_hs_b[(size_t)(SN + 1) * BN * HN];
__device__ float g_c[2 * BN * HN];                     // cell state (plain layout)
// Pre-packed tf32 weights, perm16'd k: [dir][n = j*4+gate][k'], k<512 Wh, k>=512 Wx
__device__ float g_w[(size_t)2 * 2048 * 640];
__device__ float g_wfc[(size_t)VN * 1024];             // perm16'd [v][k']

__device__ __forceinline__ float to_tf32(float x) {
    float r;
    asm("cvt.rna.tf32.f32 %0, %1;" : "=f"(r) : "f"(x));
    return r;
}

__device__ __host__ __forceinline__ int perm16(int c) { return (c & 3) * 4 + (c >> 2); }

__device__ __forceinline__ void mma_tf32(float* d, const unsigned* a, const unsigned* b) {
    asm volatile(
        "mma.sync.aligned.m16n8k8.row.col.f32.tf32.tf32.f32 "
        "{%0,%1,%2,%3}, {%4,%5,%6,%7}, {%8,%9}, {%0,%1,%2,%3};\n"
        : "+f"(d[0]), "+f"(d[1]), "+f"(d[2]), "+f"(d[3])
        : "r"(a[0]), "r"(a[1]), "r"(a[2]), "r"(a[3]),
          "r"(b[0]), "r"(b[1]));
}

__device__ __forceinline__ float sigmf(float x) { return 1.0f / (1.0f + expf(-x)); }

__global__ void init_kernel() {
    int i = blockIdx.x * blockDim.x + threadIdx.x;
    if (i < BN * HN) { g_hs_f[i] = 0.f; g_hs_b[i] = 0.f; }
    if (i < 2 * BN * HN) g_c[i] = 0.f;
}

// Pack [Wh | Wx] -> tf32, n = j*4+gate, k' = perm16 within 16-chunks.
__global__ void pack_w_kernel(const float* __restrict__ Wh_f, const float* __restrict__ Wx_f,
                              const float* __restrict__ Wh_b, const float* __restrict__ Wx_b) {
    size_t i = (size_t)blockIdx.x * blockDim.x + threadIdx.x;
    const size_t total = (size_t)2 * 2048 * 640;
    if (i >= total) return;
    int kp = (int)(i % 640);
    int n = (int)((i / 640) % 2048);
    int d = (int)(i / ((size_t)640 * 2048));
    int k = (kp & ~15) + perm16(kp & 15);   // perm16 is an involution
    int j = n >> 2, gate = n & 3;
    const float* Wh = d ? Wh_b : Wh_f;
    const float* Wx = d ? Wx_b : Wx_f;
    float v = (k < 512) ? Wh[((size_t)gate * HN + j) * HN + k]
                        : Wx[((size_t)gate * HN + j) * VN + (k - 512)];
    g_w[i] = to_tf32(v);
}

__global__ void pack_wfc_kernel(const float* __restrict__ Wfc) {
    int i = blockIdx.x * blockDim.x + threadIdx.x;
    if (i >= VN * 1024) return;
    int kp = i & 1023, v = i >> 10;
    int k = (kp & ~15) + perm16(kp & 15);
    g_wfc[i] = to_tf32(Wfc[v * 1024 + k]);
}

// ============================================================================
// step_kernel: one recurrence step, both directions (blockIdx.z).
// CTA tile 64 batch x 256 gemm cols (64 neurons x 4 gates), K=640.
// 512 threads = 16 warps (2m x 8n), warp tile 32x32.
// A (h_prev) via smem (perm16 + row-swizzle, LDS.128 fragments), loaded by
// warps 0-7 only. B (weights) direct from L2 as LDG.128 (pre-permuted g_w).
// ============================================================================
__global__ __launch_bounds__(512) void step_kernel(
    int t, const int* __restrict__ x,
    const float* __restrict__ bx_f, const float* __restrict__ bh_f,
    const float* __restrict__ bx_b, const float* __restrict__ bh_b) {
    __shared__ __align__(16) float As[2][64 * 16];
    __shared__ __align__(16) float bsum[256];

    const int tid = threadIdx.x;
    const int d = blockIdx.z;
    const int b0 = blockIdx.x * 64;
    const int j0 = blockIdx.y * 64;   // first neuron of this CTA
    const int t_eff = d ? (SN - 1 - t) : t;

    const float* __restrict__ bxp = d ? bx_b : bx_f;
    const float* __restrict__ bhp = d ? bh_b : bh_f;
    float* hs = d ? g_hs_b : g_hs_f;
    float* cst = g_c + (size_t)d * BN * HN;
    const float* hprev = hs + (size_t)t * BN * HN;
    float* hout = hs + (size_t)(t + 1) * BN * HN;

    if (tid < 256) {   // per-col bias sums (col n = jj*4+gate)
        int jj = tid >> 2, gate = tid & 3, j = j0 + jj;
        bsum[tid] = bxp[gate * HN + j] + bhp[gate * HN + j];
    }

    const bool lactive = (tid < 256);                // A loader: warps 0-7
    const int lrow = tid >> 2, lseg = tid & 3;       // 1 float4/thread (64x16 chunk)
    const int w = tid >> 5, lane = tid & 31;
    const int wm = w & 1, wn = w >> 1;               // 2x8 warp grid, warp tile 32x32
    const int gr = lane >> 2, q = lane & 3;
    const int swz = (gr >> 1) & 3;
    const int stsOff = lactive ? (lrow * 16 + 4 * (lseg ^ ((lrow >> 1) & 3))) : 0;
    const int aBase0 = wm * 512 + gr * 16 + 4 * (q ^ swz);  // +wm*32 rows

    const float* aRow = hprev + (size_t)(b0 + (lactive ? lrow : 0)) * HN;  // perm'd tf32
    const int xv = lactive ? x[(b0 + lrow) * SN + t_eff] : -1;
    const float* bPtr = g_w + ((size_t)d * 2048 + (size_t)j0 * 4 + wn * 32 + gr) * 640 + 4 * q;

    float acc[2][4][4];
#pragma unroll
    for (int i = 0; i < 2; i++)
#pragma unroll
        for (int jx = 0; jx < 4; jx++)
#pragma unroll
            for (int kx = 0; kx < 4; kx++) acc[i][jx][kx] = 0.f;

    float4 bF[2][4], rA;

#define LOADA(ch, dst)                                                                \
    if (lactive) {                                                                    \
        if ((ch) < 32) {                                                              \
            dst = *(const float4*)(aRow + (ch) * 16 + lseg * 4);                      \
        } else {                                                                      \
            int kb = ((ch) - 32) * 16 + lseg; /* component j -> vocab kb + 4j */      \
            dst = make_float4(xv == kb ? 1.f : 0.f, xv == kb + 4 ? 1.f : 0.f,         \
                              xv == kb + 8 ? 1.f : 0.f, xv == kb + 12 ? 1.f : 0.f);   \
        }                                                                             \
    }
#define LOADB(ch, buf)                                                                \
    {                                                                                 \
        _Pragma("unroll")                                                             \
        for (int tn = 0; tn < 4; tn++)                                                \
            bF[buf][tn] = *(const float4*)(bPtr + (size_t)tn * 8 * 640 + (ch) * 16);  \
    }
#define COMPUTE(p, bb)                                                                \
    {                                                                                 \
        const float* S = As[p];                                                       \
        float4 a0[2], a1[2];                                                          \
        _Pragma("unroll")                                                             \
        for (int tm = 0; tm < 2; tm++) {                                              \
            a0[tm] = *(const float4*)(S + tm * 256 + aBase0);                         \
            a1[tm] = *(const float4*)(S + tm * 256 + aBase0 + 128);                   \
        }                                                                             \
        _Pragma("unroll")                                                             \
        for (int tm = 0; tm < 2; tm++) {                                              \
            unsigned af0[4] = {__float_as_uint(a0[tm].x), __float_as_uint(a1[tm].x),  \
                               __float_as_uint(a0[tm].y), __float_as_uint(a1[tm].y)}; \
            unsigned af1[4] = {__float_as_uint(a0[tm].z), __float_as_uint(a1[tm].z),  \
                               __float_as_uint(a0[tm].w), __float_as_uint(a1[tm].w)}; \
            _Pragma("unroll")                                                         \
            for (int tn = 0; tn < 4; tn++) {                                          \
                unsigned bk0[2] = {__float_as_uint(bF[bb][tn].x),                     \
                                   __float_as_uint(bF[bb][tn].y)};                    \
                unsigned bk1[2] = {__float_as_uint(bF[bb][tn].z),                     \
                                   __float_as_uint(bF[bb][tn].w)};                    \
                mma_tf32(acc[tm][tn], af0, bk0);                                      \
                mma_tf32(acc[tm][tn], af1, bk1);                                      \
            }                                                                         \
        }                                                                             \
    }

    LOADA(0, rA);
    LOADB(0, 0);
    for (int kc = 0; kc < 40; kc += 2) {
        // phase 0: chunk kc
        if (lactive) *(float4*)(&As[0][stsOff]) = rA;
        LOADA(kc + 1, rA);
        LOADB(kc + 1, 1);
        __syncthreads();
        COMPUTE(0, 0);
        // phase 1: chunk kc+1
        if (lactive) *(float4*)(&As[1][stsOff]) = rA;
        if (kc + 2 < 40) { LOADA(kc + 2, rA); LOADB(kc + 2, 0); }
        __syncthreads();
        COMPUTE(1, 1);
    }
#undef LOADA
#undef LOADB
#undef COMPUTE

    // Epilogue: lane pair (l, l^1) exchanges to gather all 4 gates of a cell.
#pragma unroll
    for (int tm = 0; tm < 2; tm++) {
        int rbase = b0 + wm * 32 + tm * 16 + gr;
#pragma unroll
        for (int tn = 0; tn < 4; tn++) {
            float c0 = acc[tm][tn][0], c1 = acc[tm][tn][1];
            float c2 = acc[tm][tn][2], c3 = acc[tm][tn][3];
            float e0 = __shfl_xor_sync(0xffffffffu, c0, 1);
            float e1 = __shfl_xor_sync(0xffffffffu, c1, 1);
            float e2 = __shfl_xor_sync(0xffffffffu, c2, 1);
            float e3 = __shfl_xor_sync(0xffffffffu, c3, 1);
            float iv, fv, ov, gv;
            int brow;
            if ((q & 1) == 0) { iv = c0; fv = c1; ov = e0; gv = e1; brow = rbase; }
            else              { iv = e2; fv = e3; ov = c2; gv = c3; brow = rbase + 8; }
            int jj4 = wn * 32 + tn * 8 + (q >> 1) * 4;
            float4 bs = *(const float4*)&bsum[jj4];
            float gi = sigmf(iv + bs.x);
            float gf = sigmf(fv + bs.y);
            float go = sigmf(ov + bs.z);
            float gg = tanhf(gv + bs.w);
            int jg = j0 + (jj4 >> 2);
            int kp = (jg & ~15) | perm16(jg & 15);   // store h permuted
            size_t ci = (size_t)brow * HN + jg;
            float cn = gf * cst[ci] + gi * gg;
            cst[ci] = cn;
            hout[(size_t)brow * HN + kp] = to_tf32(go * tanhf(cn));
        }
    }
}

// ============================================================================
// fc_kernel: y[b,s,v] = [hf(s)|hb(s)] . Wfc[v,:] + bfc[v]. K=1024, 64 chunks.
// CTA 128 rows x 128 cols, 8 warps 2x4, warp tile 64x32. A and B via smem
// with perm16 + swizzle (both stored pre-permuted in global).
// ============================================================================
__global__ __launch_bounds__(256) void fc_kernel(const float* __restrict__ bfc,
                                                 float* __restrict__ y) {
    __shared__ __align__(16) float As[2][128 * 16];
    __shared__ __align__(16) float Bs[2][128 * 16];
    __shared__ float bsh[128];

    const int tid = threadIdx.x;
    const int s = blockIdx.x >> 2;
    const int b0r = (blockIdx.x & 3) * 128;

    const float* Af = g_hs_f + (size_t)(s + 1) * BN * HN;
    const float* Ab = g_hs_b + (size_t)(SN - s) * BN * HN;

    if (tid < 128) bsh[tid] = bfc[tid];

    const int lrow = tid >> 1;              // loader: 2 float4 per thread
    const int sb = (tid & 1) * 2;           // seg base
    const int lswz = (lrow >> 1) & 3;
    const int o0 = lrow * 16 + 4 * (sb ^ lswz);
    const int o1 = lrow * 16 + 4 * ((sb + 1) ^ lswz);

    const int warp = tid >> 5, lane = tid & 31;
    const int wm = warp >> 2, wn = warp & 3;
    const int gr = lane >> 2, q = lane & 3;
    const int swz = (gr >> 1) & 3;
    const int aBase0 = gr * 16 + 4 * (q ^ swz);

    const float* afRow = Af + (size_t)(b0r + lrow) * HN;
    const float* abRow = Ab + (size_t)(b0r + lrow) * HN;
    const float* bRow = g_wfc + (size_t)lrow * 1024;

    float acc[4][4][4];
#pragma unroll
    for (int i = 0; i < 4; i++)
#pragma unroll
        for (int jx = 0; jx < 4; jx++)
#pragma unroll
            for (int kx = 0; kx < 4; kx++) acc[i][jx][kx] = 0.f;

    float4 rA0, rA1, rB0, rB1;

#define LOADFC(ch)                                                              \
    {                                                                           \
        int kp = (ch) * 16 + sb * 4;                                            \
        const float* srcA = (kp < 512) ? (afRow + kp) : (abRow + (kp - 512));   \
        rA0 = *(const float4*)(srcA);                                           \
        rA1 = *(const float4*)(srcA + 4);                                       \
        rB0 = *(const float4*)(bRow + kp);                                      \
        rB1 = *(const float4*)(bRow + kp + 4);                                  \
    }
#define STORFC(p)                                                               \
    {                                                                           \
        *(float4*)(&As[p][o0]) = rA0;                                           \
        *(float4*)(&As[p][o1]) = rA1;                                           \
        *(float4*)(&Bs[p][o0]) = rB0;                                           \
        *(float4*)(&Bs[p][o1]) = rB1;                                           \
    }
#define COMPFC(p)                                                               \
    {                                                                           \
        const float* SA = As[p];                                                \
        const float* SB = Bs[p];                                                \
        float4 a0[4], a1[4], bq[4];                                             \
        _Pragma("unroll")                                                       \
        for (int tm = 0; tm < 4; tm++) {                                        \
            a0[tm] = *(const float4*)(SA + wm * 1024 + tm * 256 + aBase0);      \
            a1[tm] = *(const float4*)(SA + wm * 1024 + tm * 256 + aBase0 + 128);\
        }                                                                       \
        _Pragma("unroll")                                                       \
        for (int tn = 0; tn < 4; tn++)                                          \
            bq[tn] = *(const float4*)(SB + wn * 512 + tn * 128 + aBase0);       \
        _Pragma("unroll")                                                       \
        for (int tm = 0; tm < 4; tm++) {                                        \
            unsigned af0[4] = {__float_as_uint(a0[tm].x), __float_as_uint(a1[tm].x),\
                               __float_as_uint(a0[tm].y), __float_as_uint(a1[tm].y)};\
            unsigned af1[4] = {__float_as_uint(a0[tm].z), __float_as_uint(a1[tm].z),\
                               __float_as_uint(a0[tm].w), __float_as_uint(a1[tm].w)};\
            _Pragma("unroll")                                                   \
            for (int tn = 0; tn < 4; tn++) {                                    \
                unsigned bk0[2] = {__float_as_uint(bq[tn].x), __float_as_uint(bq[tn].y)};\
                unsigned bk1[2] = {__float_as_uint(bq[tn].z), __float_as_uint(bq[tn].w)};\
                mma_tf32(acc[tm][tn], af0, bk0);                                \
                mma_tf32(acc[tm][tn], af1, bk1);                                \
            }                                                                   \
        }                                                                       \
    }

    LOADFC(0);
    for (int kc = 0; kc < 64; kc += 2) {
        STORFC(0);
        LOADFC(kc + 1);
        __syncthreads();
        COMPFC(0);
        STORFC(1);
        if (kc + 2 < 64) LOADFC(kc + 2);
        __syncthreads();
        COMPFC(1);
    }
#undef LOADFC
#undef STORFC
#undef COMPFC

#pragma unroll
    for (int tm = 0; tm < 4; tm++) {
        int b = b0r + wm * 64 + tm * 16 + gr;
#pragma unroll
        for (int tn = 0; tn < 4; tn++) {
            int n0 = wn * 32 + tn * 8 + 2 * q;
            float2 w0 = make_float2(acc[tm][tn][0] + bsh[n0], acc[tm][tn][1] + bsh[n0 + 1]);
            *(float2*)(y + ((size_t)b * SN + s) * VN + n0) = w0;
            float2 w1 = make_float2(acc[tm][tn][2] + bsh[n0], acc[tm][tn][3] + bsh[n0 + 1]);
            *(float2*)(y + ((size_t)(b + 8) * SN + s) * VN + n0) = w1;
        }
    }
}

extern "C" void kernel_launch(void* const* d_in, const int* in_sizes, int n_in,
                              void* d_out, int out_size) {
    const int*   x    = (const int*)d_in[0];
    const float* Wx_f = (const float*)d_in[1];
    const float* Wh_f = (const float*)d_in[2];
    const float* bx_f = (const float*)d_in[3];
    const float* bh_f = (const float*)d_in[4];
    const float* Wx_b = (const float*)d_in[5];
    const float* Wh_b = (const float*)d_in[6];
    const float* bx_b = (const float*)d_in[7];
    const float* bh_b = (const float*)d_in[8];
    const float* Wfc  = (const float*)d_in[9];
    const float* bfc  = (const float*)d_in[10];
    float* y = (float*)d_out;

    init_kernel<<<2048, 256>>>();
    pack_w_kernel<<<(2 * 2048 * 640 + 255) / 256, 256>>>(Wh_f, Wx_f, Wh_b, Wx_b);
    pack_wfc_kernel<<<(VN * 1024 + 255) / 256, 256>>>(Wfc);

    // 256 sequential recurrence steps; both directions fused per launch.
    dim3 g(8, 8, 2);  // 8 batch tiles x 8 neuron tiles x 2 directions = 128 CTAs
    for (int t = 0; t < SN; t++)
        step_kernel<<<g, 512>>>(t, x, bx_f, bh_f, bx_b, bh_b);

    // final projection over all (s, b)
    fc_kernel<<<1024, 256>>>(bfc, y);
}

// round 12
// speedup vs baseline: 1.6028x; 1.0963x over previous
#include <cuda_runtime.h>
#include <cstdint>
#include <cstddef>

// Problem dims
#define VN 128
#define HN 512
#define BN 512
#define SN 256

// Static scratch (module-load allocated; no runtime allocation)
// h is stored tf32-rounded AND perm16-permuted within each 16-k chunk.
__device__ float g_hs_f[(size_t)(SN + 1) * BN * HN];
__device__ float g_hs_b[(size_t)(SN + 1) * BN * HN];
__device__ float g_c[2 * BN * HN];                     // cell state (plain layout)
// Pre-packed tf32 weights, perm16'd k: [dir][n = j*4+gate][k'], k<512 Wh, k>=512 Wx
__device__ float g_w[(size_t)2 * 2048 * 640];
__device__ float g_wfc[(size_t)VN * 1024];             // perm16'd [v][k']

__device__ __forceinline__ float to_tf32(float x) {
    float r;
    asm("cvt.rna.tf32.f32 %0, %1;" : "=f"(r) : "f"(x));
    return r;
}

__device__ __host__ __forceinline__ int perm16(int c) { return (c & 3) * 4 + (c >> 2); }

__device__ __forceinline__ void mma_tf32(float* d, const unsigned* a, const unsigned* b) {
    asm volatile(
        "mma.sync.aligned.m16n8k8.row.col.f32.tf32.tf32.f32 "
        "{%0,%1,%2,%3}, {%4,%5,%6,%7}, {%8,%9}, {%0,%1,%2,%3};\n"
        : "+f"(d[0]), "+f"(d[1]), "+f"(d[2]), "+f"(d[3])
        : "r"(a[0]), "r"(a[1]), "r"(a[2]), "r"(a[3]),
          "r"(b[0]), "r"(b[1]));
}

__device__ __forceinline__ float sigmf(float x) { return 1.0f / (1.0f + expf(-x)); }

__global__ void init_kernel() {
    int i = blockIdx.x * blockDim.x + threadIdx.x;
    if (i < BN * HN) { g_hs_f[i] = 0.f; g_hs_b[i] = 0.f; }
    if (i < 2 * BN * HN) g_c[i] = 0.f;
}

// Pack [Wh | Wx] -> tf32, n = j*4+gate, k' = perm16 within 16-chunks.
__global__ void pack_w_kernel(const float* __restrict__ Wh_f, const float* __restrict__ Wx_f,
                              const float* __restrict__ Wh_b, const float* __restrict__ Wx_b) {
    size_t i = (size_t)blockIdx.x * blockDim.x + threadIdx.x;
    const size_t total = (size_t)2 * 2048 * 640;
    if (i >= total) return;
    int kp = (int)(i % 640);
    int n = (int)((i / 640) % 2048);
    int d = (int)(i / ((size_t)640 * 2048));
    int k = (kp & ~15) + perm16(kp & 15);   // perm16 is an involution
    int j = n >> 2, gate = n & 3;
    const float* Wh = d ? Wh_b : Wh_f;
    const float* Wx = d ? Wx_b : Wx_f;
    float v = (k < 512) ? Wh[((size_t)gate * HN + j) * HN + k]
                        : Wx[((size_t)gate * HN + j) * VN + (k - 512)];
    g_w[i] = to_tf32(v);
}

__global__ void pack_wfc_kernel(const float* __restrict__ Wfc) {
    int i = blockIdx.x * blockDim.x + threadIdx.x;
    if (i >= VN * 1024) return;
    int kp = i & 1023, v = i >> 10;
    int k = (kp & ~15) + perm16(kp & 15);
    g_wfc[i] = to_tf32(Wfc[v * 1024 + k]);
}

// ============================================================================
// step_kernel: one recurrence step, both directions (blockIdx.z).
// CTA tile 64 batch x 128 gemm cols (32 neurons x 4 gates), K=640.
// 256 threads = 8 warps (2m x 4n), warp tile 32x32. Grid 256 CTAs -> 2/SM.
// A (h_prev) via smem ring (perm16 + row-swizzle, LDS.128 fragments),
// loaded by ALL threads. B (weights) direct from L2 via LDG.128 (g_w),
// staggered 1.5-iteration prefetch. One __syncthreads per 2 chunks.
// ============================================================================
__global__ __launch_bounds__(256) void step_kernel(
    int t, const int* __restrict__ x,
    const float* __restrict__ bx_f, const float* __restrict__ bh_f,
    const float* __restrict__ bx_b, const float* __restrict__ bh_b) {
    __shared__ __align__(16) float As[2][2][64 * 16];   // [buf][chunk-in-pair][...]
    __shared__ __align__(16) float bsum[128];

    const int tid = threadIdx.x;
    const int d = blockIdx.z;
    const int b0 = blockIdx.x * 64;
    const int j0 = blockIdx.y * 32;   // first neuron of this CTA
    const int t_eff = d ? (SN - 1 - t) : t;

    const float* __restrict__ bxp = d ? bx_b : bx_f;
    const float* __restrict__ bhp = d ? bh_b : bh_f;
    float* hs = d ? g_hs_b : g_hs_f;
    float* cst = g_c + (size_t)d * BN * HN;
    const float* hprev = hs + (size_t)t * BN * HN;
    float* hout = hs + (size_t)(t + 1) * BN * HN;

    if (tid < 128) {   // per-col bias sums (col n = jj*4+gate)
        int jj = tid >> 2, gate = tid & 3, j = j0 + jj;
        bsum[tid] = bxp[gate * HN + j] + bhp[gate * HN + j];
    }

    const int lrow = tid >> 2, lseg = tid & 3;       // A loader: 1 float4/thread/chunk
    const int w = tid >> 5, lane = tid & 31;
    const int wm = w >> 2, wn = w & 3;               // 2x4 warp grid, warp tile 32x32
    const int gr = lane >> 2, q = lane & 3;
    const int swz = (gr >> 1) & 3;
    const int stsOff = lrow * 16 + 4 * (lseg ^ ((lrow >> 1) & 3));
    const int aBase0 = wm * 512 + gr * 16 + 4 * (q ^ swz);  // +wm*32 rows

    const float* aRow = hprev + (size_t)(b0 + lrow) * HN;   // perm'd tf32
    const int xv = x[(b0 + lrow) * SN + t_eff];
    const float* bPtr = g_w + ((size_t)d * 2048 + (size_t)j0 * 4 + wn * 32 + gr) * 640 + 4 * q;

    float acc[2][4][4];
#pragma unroll
    for (int i = 0; i < 2; i++)
#pragma unroll
        for (int jx = 0; jx < 4; jx++)
#pragma unroll
            for (int kx = 0; kx < 4; kx++) acc[i][jx][kx] = 0.f;

    float4 bF[2][4], rA0, rA1;

#define LOADA(ch, dst)                                                                \
    {                                                                                 \
        if ((ch) < 32) {                                                              \
            dst = *(const float4*)(aRow + (ch) * 16 + lseg * 4);                      \
        } else {                                                                      \
            int kb = ((ch) - 32) * 16 + lseg; /* component j -> vocab kb + 4j */      \
            dst = make_float4(xv == kb ? 1.f : 0.f, xv == kb + 4 ? 1.f : 0.f,         \
                              xv == kb + 8 ? 1.f : 0.f, xv == kb + 12 ? 1.f : 0.f);   \
        }                                                                             \
    }
#define LOADB(ch, buf)                                                                \
    {                                                                                 \
        _Pragma("unroll")                                                             \
        for (int tn = 0; tn < 4; tn++)                                                \
            bF[buf][tn] = *(const float4*)(bPtr + (size_t)tn * 8 * 640 + (ch) * 16);  \
    }
#define COMPUTE(S, bb)                                                                \
    {                                                                                 \
        float4 a0[2], a1[2];                                                          \
        _Pragma("unroll")                                                             \
        for (int tm = 0; tm < 2; tm++) {                                              \
            a0[tm] = *(const float4*)((S) + tm * 256 + aBase0);                       \
            a1[tm] = *(const float4*)((S) + tm * 256 + aBase0 + 128);                 \
        }                                                                             \
        _Pragma("unroll")                                                             \
        for (int tm = 0; tm < 2; tm++) {                                              \
            unsigned af0[4] = {__float_as_uint(a0[tm].x), __float_as_uint(a1[tm].x),  \
                               __float_as_uint(a0[tm].y), __float_as_uint(a1[tm].y)}; \
            unsigned af1[4] = {__float_as_uint(a0[tm].z), __float_as_uint(a1[tm].z),  \
                               __float_as_uint(a0[tm].w), __float_as_uint(a1[tm].w)}; \
            _Pragma("unroll")                                                         \
            for (int tn = 0; tn < 4; tn++) {                                          \
                unsigned bk0[2] = {__float_as_uint(bF[bb][tn].x),                     \
                                   __float_as_uint(bF[bb][tn].y)};                    \
                unsigned bk1[2] = {__float_as_uint(bF[bb][tn].z),                     \
                                   __float_as_uint(bF[bb][tn].w)};                    \
                mma_tf32(acc[tm][tn], af0, bk0);                                      \
                mma_tf32(acc[tm][tn], af1, bk1);                                      \
            }                                                                         \
        }                                                                             \
    }

    LOADA(0, rA0);
    LOADA(1, rA1);
    LOADB(0, 0);
    for (int kc = 0; kc < 40; kc += 2) {
        const int p = (kc >> 1) & 1;
        // stage this pair of chunks
        *(float4*)(&As[p][0][stsOff]) = rA0;
        *(float4*)(&As[p][1][stsOff]) = rA1;
        // prefetch B(kc+1) and A(kc+2, kc+3) before the barrier
        LOADB(kc + 1, 1);
        if (kc + 2 < 40) { LOADA(kc + 2, rA0); LOADA(kc + 3, rA1); }
        __syncthreads();
        COMPUTE(As[p][0], 0);
        if (kc + 2 < 40) LOADB(kc + 2, 0);   // next pair's first B, mid-iteration
        COMPUTE(As[p][1], 1);
    }
#undef LOADA
#undef LOADB
#undef COMPUTE

    // Epilogue: lane pair (l, l^1) exchanges to gather all 4 gates of a cell.
#pragma unroll
    for (int tm = 0; tm < 2; tm++) {
        int rbase = b0 + wm * 32 + tm * 16 + gr;
#pragma unroll
        for (int tn = 0; tn < 4; tn++) {
            float c0 = acc[tm][tn][0], c1 = acc[tm][tn][1];
            float c2 = acc[tm][tn][2], c3 = acc[tm][tn][3];
            float e0 = __shfl_xor_sync(0xffffffffu, c0, 1);
            float e1 = __shfl_xor_sync(0xffffffffu, c1, 1);
            float e2 = __shfl_xor_sync(0xffffffffu, c2, 1);
            float e3 = __shfl_xor_sync(0xffffffffu, c3, 1);
            float iv, fv, ov, gv;
            int brow;
            if ((q & 1) == 0) { iv = c0; fv = c1; ov = e0; gv = e1; brow = rbase; }
            else              { iv = e2; fv = e3; ov = c2; gv = c3; brow = rbase + 8; }
            int jj4 = wn * 32 + tn * 8 + (q >> 1) * 4;
            float4 bs = *(const float4*)&bsum[jj4];
            float gi = sigmf(iv + bs.x);
            float gf = sigmf(fv + bs.y);
            float go = sigmf(ov + bs.z);
            float gg = tanhf(gv + bs.w);
            int jg = j0 + (jj4 >> 2);
            int kp = (jg & ~15) | perm16(jg & 15);   // store h permuted
            size_t ci = (size_t)brow * HN + jg;
            float cn = gf * cst[ci] + gi * gg;
            cst[ci] = cn;
            hout[(size_t)brow * HN + kp] = to_tf32(go * tanhf(cn));
        }
    }
}

// ============================================================================
// fc_kernel: y[b,s,v] = [hf(s)|hb(s)] . Wfc[v,:] + bfc[v]. K=1024, 64 chunks.
// CTA 128 rows x 128 cols, 8 warps 2x4, warp tile 64x32. A and B via smem
// with perm16 + swizzle (both stored pre-permuted in global).
// ============================================================================
__global__ __launch_bounds__(256) void fc_kernel(const float* __restrict__ bfc,
                                                 float* __restrict__ y) {
    __shared__ __align__(16) float As[2][128 * 16];
    __shared__ __align__(16) float Bs[2][128 * 16];
    __shared__ float bsh[128];

    const int tid = threadIdx.x;
    const int s = blockIdx.x >> 2;
    const int b0r = (blockIdx.x & 3) * 128;

    const float* Af = g_hs_f + (size_t)(s + 1) * BN * HN;
    const float* Ab = g_hs_b + (size_t)(SN - s) * BN * HN;

    if (tid < 128) bsh[tid] = bfc[tid];

    const int lrow = tid >> 1;              // loader: 2 float4 per thread
    const int sb = (tid & 1) * 2;           // seg base
    const int lswz = (lrow >> 1) & 3;
    const int o0 = lrow * 16 + 4 * (sb ^ lswz);
    const int o1 = lrow * 16 + 4 * ((sb + 1) ^ lswz);

    const int warp = tid >> 5, lane = tid & 31;
    const int wm = warp >> 2, wn = warp & 3;
    const int gr = lane >> 2, q = lane & 3;
    const int swz = (gr >> 1) & 3;
    const int aBase0 = gr * 16 + 4 * (q ^ swz);

    const float* afRow = Af + (size_t)(b0r + lrow) * HN;
    const float* abRow = Ab + (size_t)(b0r + lrow) * HN;
    const float* bRow = g_wfc + (size_t)lrow * 1024;

    float acc[4][4][4];
#pragma unroll
    for (int i = 0; i < 4; i++)
#pragma unroll
        for (int jx = 0; jx < 4; jx++)
#pragma unroll
            for (int kx = 0; kx < 4; kx++) acc[i][jx][kx] = 0.f;

    float4 rA0, rA1, rB0, rB1;

#define LOADFC(ch)                                                              \
    {                                                                           \
        int kp = (ch) * 16 + sb * 4;                                            \
        const float* srcA = (kp < 512) ? (afRow + kp) : (abRow + (kp - 512));   \
        rA0 = *(const float4*)(srcA);                                           \
        rA1 = *(const float4*)(srcA + 4);                                       \
        rB0 = *(const float4*)(bRow + kp);                                      \
        rB1 = *(const float4*)(bRow + kp + 4);                                  \
    }
#define STORFC(p)                                                               \
    {                                                                           \
        *(float4*)(&As[p][o0]) = rA0;                                           \
        *(float4*)(&As[p][o1]) = rA1;                                           \
        *(float4*)(&Bs[p][o0]) = rB0;                                           \
        *(float4*)(&Bs[p][o1]) = rB1;                                           \
    }
#define COMPFC(p)                                                               \
    {                                                                           \
        const float* SA = As[p];                                                \
        const float* SB = Bs[p];                                                \
        float4 a0[4], a1[4], bq[4];                                             \
        _Pragma("unroll")                                                       \
        for (int tm = 0; tm < 4; tm++) {                                        \
            a0[tm] = *(const float4*)(SA + wm * 1024 + tm * 256 + aBase0);      \
            a1[tm] = *(const float4*)(SA + wm * 1024 + tm * 256 + aBase0 + 128);\
        }                                                                       \
        _Pragma("unroll")                                                       \
        for (int tn = 0; tn < 4; tn++)                                          \
            bq[tn] = *(const float4*)(SB + wn * 512 + tn * 128 + aBase0);       \
        _Pragma("unroll")                                                       \
        for (int tm = 0; tm < 4; tm++) {                                        \
            unsigned af0[4] = {__float_as_uint(a0[tm].x), __float_as_uint(a1[tm].x),\
                               __float_as_uint(a0[tm].y), __float_as_uint(a1[tm].y)};\
            unsigned af1[4] = {__float_as_uint(a0[tm].z), __float_as_uint(a1[tm].z),\
                               __float_as_uint(a0[tm].w), __float_as_uint(a1[tm].w)};\
            _Pragma("unroll")                                                   \
            for (int tn = 0; tn < 4; tn++) {                                    \
                unsigned bk0[2] = {__float_as_uint(bq[tn].x), __float_as_uint(bq[tn].y)};\
                unsigned bk1[2] = {__float_as_uint(bq[tn].z), __float_as_uint(bq[tn].w)};\
                mma_tf32(acc[tm][tn], af0, bk0);                                \
                mma_tf32(acc[tm][tn], af1, bk1);                                \
            }                                                                   \
        }                                                                       \
    }

    LOADFC(0);
    for (int kc = 0; kc < 64; kc += 2) {
        STORFC(0);
        LOADFC(kc + 1);
        __syncthreads();
        COMPFC(0);
        STORFC(1);
        if (kc + 2 < 64) LOADFC(kc + 2);
        __syncthreads();
        COMPFC(1);
    }
#undef LOADFC
#undef STORFC
#undef COMPFC

#pragma unroll
    for (int tm = 0; tm < 4; tm++) {
        int b = b0r + wm * 64 + tm * 16 + gr;
#pragma unroll
        for (int tn = 0; tn < 4; tn++) {
            int n0 = wn * 32 + tn * 8 + 2 * q;
            float2 w0 = make_float2(acc[tm][tn][0] + bsh[n0], acc[tm][tn][1] + bsh[n0 + 1]);
            *(float2*)(y + ((size_t)b * SN + s) * VN + n0) = w0;
            float2 w1 = make_float2(acc[tm][tn][2] + bsh[n0], acc[tm][tn][3] + bsh[n0 + 1]);
            *(float2*)(y + ((size_t)(b + 8) * SN + s) * VN + n0) = w1;
        }
    }
}

extern "C" void kernel_launch(void* const* d_in, const int* in_sizes, int n_in,
                              void* d_out, int out_size) {
    const int*   x    = (const int*)d_in[0];
    const float* Wx_f = (const float*)d_in[1];
    const float* Wh_f = (const float*)d_in[2];
    const float* bx_f = (const float*)d_in[3];
    const float* bh_f = (const float*)d_in[4];
    const float* Wx_b = (const float*)d_in[5];
    const float* Wh_b = (const float*)d_in[6];
    const float* bx_b = (const float*)d_in[7];
    const float* bh_b = (const float*)d_in[8];
    const float* Wfc  = (const float*)d_in[9];
    const float* bfc  = (const float*)d_in[10];
    float* y = (float*)d_out;

    init_kernel<<<2048, 256>>>();
    pack_w_kernel<<<(2 * 2048 * 640 + 255) / 256, 256>>>(Wh_f, Wx_f, Wh_b, Wx_b);
    pack_wfc_kernel<<<(VN * 1024 + 255) / 256, 256>>>(Wfc);

    // 256 sequential recurrence steps; both directions fused per launch.
    dim3 g(8, 16, 2);  // 8 batch tiles x 16 neuron tiles x 2 directions = 256 CTAs (2/SM)
    for (int t = 0; t < SN; t++)
        step_kernel<<<g, 256>>>(t, x, bx_f, bh_f, bx_b, bh_b);

    // final projection over all (s, b)
    fc_kernel<<<1024, 256>>>(bfc, y);
}

// round 14
// speedup vs baseline: 2.3654x; 1.4758x over previous
#include <cuda_runtime.h>
#include <cuda_fp16.h>
#include <cstdint>
#include <cstddef>

// Problem dims
#define VN 128
#define HN 512
#define BN 512
#define SN 256

// Static scratch (module-load allocated; no runtime allocation)
// h is stored fp16, perm32-permuted within each 32-k chunk.
__device__ __half g_hs_f[(size_t)(SN + 1) * BN * HN];
__device__ __half g_hs_b[(size_t)(SN + 1) * BN * HN];
__device__ float  g_c[2 * BN * HN];                    // cell state (plain layout, fp32)
// Pre-packed fp16 weights, perm32'd k: [dir][n = j*4+gate][k'], k<512 Wh, k>=512 Wx
__device__ __half g_w[(size_t)2 * 2048 * 640];
__device__ __half g_wfc[(size_t)VN * 1024];            // perm32'd [v][k']

// perm32: slot s = q*8 + j  <->  k = (j>>2)*16 + ((j>>1)&1)*8 + (j&1) + 2*q
__device__ __host__ __forceinline__ int slot2k(int s) {
    int q = s >> 3, j = s & 7;
    return (j >> 2) * 16 + ((j >> 1) & 1) * 8 + (j & 1) + 2 * q;
}
__device__ __forceinline__ int k2slot(int k) {
    int q = (k & 7) >> 1, b1 = k & 1, b2 = (k >> 3) & 1, b4 = (k >> 4) & 1;
    return q * 8 + b4 * 4 + b2 * 2 + b1;
}

__device__ __forceinline__ void mma_f16(float* d, const unsigned* a, const unsigned* b) {
    asm volatile(
        "mma.sync.aligned.m16n8k16.row.col.f32.f16.f16.f32 "
        "{%0,%1,%2,%3}, {%4,%5,%6,%7}, {%8,%9}, {%0,%1,%2,%3};\n"
        : "+f"(d[0]), "+f"(d[1]), "+f"(d[2]), "+f"(d[3])
        : "r"(a[0]), "r"(a[1]), "r"(a[2]), "r"(a[3]),
          "r"(b[0]), "r"(b[1]));
}

__device__ __forceinline__ float sigmf(float x) { return 1.0f / (1.0f + expf(-x)); }

__global__ void init_kernel() {
    int i = blockIdx.x * blockDim.x + threadIdx.x;
    if (i < BN * HN) {
        g_hs_f[i] = __ushort_as_half(0);
        g_hs_b[i] = __ushort_as_half(0);
    }
    if (i < 2 * BN * HN) g_c[i] = 0.f;
}

// Pack [Wh | Wx] -> fp16, n = j*4+gate, k' = perm32 within 32-chunks.
__global__ void pack_w_kernel(const float* __restrict__ Wh_f, const float* __restrict__ Wx_f,
                              const float* __restrict__ Wh_b, const float* __restrict__ Wx_b) {
    size_t i = (size_t)blockIdx.x * blockDim.x + threadIdx.x;
    const size_t total = (size_t)2 * 2048 * 640;
    if (i >= total) return;
    int kp = (int)(i % 640);
    int n = (int)((i / 640) % 2048);
    int d = (int)(i / ((size_t)640 * 2048));
    int k = (kp & ~31) + slot2k(kp & 31);
    int j = n >> 2, gate = n & 3;
    const float* Wh = d ? Wh_b : Wh_f;
    const float* Wx = d ? Wx_b : Wx_f;
    float v = (k < 512) ? Wh[((size_t)gate * HN + j) * HN + k]
                        : Wx[((size_t)gate * HN + j) * VN + (k - 512)];
    g_w[i] = __float2half_rn(v);
}

__global__ void pack_wfc_kernel(const float* __restrict__ Wfc) {
    int i = blockIdx.x * blockDim.x + threadIdx.x;
    if (i >= VN * 1024) return;
    int kp = i & 1023, v = i >> 10;
    int k = (kp & ~31) + slot2k(kp & 31);
    g_wfc[i] = __float2half_rn(Wfc[v * 1024 + k]);
}

// ============================================================================
// step_kernel: one recurrence step, both directions (blockIdx.z).
// CTA tile 64 batch x 128 gemm cols (32 neurons x 4 gates), K=640 fp16.
// 256 threads = 8 warps (2m x 4n), warp tile 32x32, MMA m16n8k16.
// 20 chunks of K=32; pairs share one __syncthreads. A via smem (perm32 +
// row-swizzle, LDS.128 = full k32 fragment set). B direct LDG.128 from g_w.
// ============================================================================
__global__ __launch_bounds__(256, 2) void step_kernel(
    int t, const int* __restrict__ x,
    const float* __restrict__ bx_f, const float* __restrict__ bh_f,
    const float* __restrict__ bx_b, const float* __restrict__ bh_b) {
    __shared__ __align__(16) __half As[2][2][64 * 32];   // [buf][chunk-in-pair][...]
    __shared__ __align__(16) float bsum[128];

    const int tid = threadIdx.x;
    const int d = blockIdx.z;
    const int b0 = blockIdx.x * 64;
    const int j0 = blockIdx.y * 32;   // first neuron of this CTA
    const int t_eff = d ? (SN - 1 - t) : t;

    const float* __restrict__ bxp = d ? bx_b : bx_f;
    const float* __restrict__ bhp = d ? bh_b : bh_f;
    __half* hs = d ? g_hs_b : g_hs_f;
    float* cst = g_c + (size_t)d * BN * HN;
    const __half* hprev = hs + (size_t)t * BN * HN;
    __half* hout = hs + (size_t)(t + 1) * BN * HN;

    if (tid < 128) {   // per-col bias sums (col n = jj*4+gate)
        int jj = tid >> 2, gate = tid & 3, j = j0 + jj;
        bsum[tid] = bxp[gate * HN + j] + bhp[gate * HN + j];
    }

    const int lrow = tid >> 2, lseg = tid & 3;       // A loader: 8 halfs/thread/chunk
    const int w = tid >> 5, lane = tid & 31;
    const int wm = w >> 2, wn = w & 3;               // 2x4 warp grid, warp tile 32x32
    const int gr = lane >> 2, q = lane & 3;
    const int swz = (gr >> 1) & 3;
    const int stsOff = lrow * 32 + 8 * (lseg ^ ((lrow >> 1) & 3));   // half units
    const int aOffBase = wm * 1024 + gr * 32 + 8 * (q ^ swz);        // +row*32 halfs

    const __half* aRow = hprev + (size_t)(b0 + lrow) * HN;
    const int xv = x[(b0 + lrow) * SN + t_eff];
    const __half* bPtr = g_w + ((size_t)d * 2048 + (size_t)j0 * 4 + wn * 32 + gr) * 640 + q * 8;

    float acc[2][4][4];
#pragma unroll
    for (int i = 0; i < 2; i++)
#pragma unroll
        for (int jx = 0; jx < 4; jx++)
#pragma unroll
            for (int kx = 0; kx < 4; kx++) acc[i][jx][kx] = 0.f;

    uint4 bF[2][4], rA0, rA1;

#define LOADA(ch, dst)                                                                \
    {                                                                                 \
        if ((ch) < 16) {                                                              \
            dst = *(const uint4*)(aRow + (ch) * 32 + lseg * 8);                       \
        } else {                                                                      \
            int kb = ((ch) - 16) * 32 + 2 * lseg;                                     \
            union { uint4 u; unsigned short us[8]; } tmp;                             \
            tmp.us[0] = (xv == kb)      ? 0x3C00 : 0;                                 \
            tmp.us[1] = (xv == kb + 1)  ? 0x3C00 : 0;                                 \
            tmp.us[2] = (xv == kb + 8)  ? 0x3C00 : 0;                                 \
            tmp.us[3] = (xv == kb + 9)  ? 0x3C00 : 0;                                 \
            tmp.us[4] = (xv == kb + 16) ? 0x3C00 : 0;                                 \
            tmp.us[5] = (xv == kb + 17) ? 0x3C00 : 0;                                 \
            tmp.us[6] = (xv == kb + 24) ? 0x3C00 : 0;                                 \
            tmp.us[7] = (xv == kb + 25) ? 0x3C00 : 0;                                 \
            dst = tmp.u;                                                              \
        }                                                                             \
    }
#define LOADB(ch, buf)                                                                \
    {                                                                                 \
        _Pragma("unroll")                                                             \
        for (int tn = 0; tn < 4; tn++)                                                \
            bF[buf][tn] = *(const uint4*)(bPtr + (size_t)tn * 8 * 640 + (ch) * 32);   \
    }
#define COMPUTE(S, bb)                                                                \
    {                                                                                 \
        _Pragma("unroll")                                                             \
        for (int tm = 0; tm < 2; tm++) {                                              \
            const __half* base = (S) + tm * 512 + aOffBase;                           \
            uint4 A0 = *(const uint4*)(base);                                         \
            uint4 A1 = *(const uint4*)(base + 256);                                   \
            unsigned af0[4] = {A0.x, A1.x, A0.y, A1.y};                               \
            unsigned af1[4] = {A0.z, A1.z, A0.w, A1.w};                               \
            _Pragma("unroll")                                                         \
            for (int tn = 0; tn < 4; tn++) {                                          \
                unsigned bk0[2] = {bF[bb][tn].x, bF[bb][tn].y};                       \
                unsigned bk1[2] = {bF[bb][tn].z, bF[bb][tn].w};                       \
                mma_f16(acc[tm][tn], af0, bk0);                                       \
                mma_f16(acc[tm][tn], af1, bk1);                                       \
            }                                                                         \
        }                                                                             \
    }

    LOADA(0, rA0);
    LOADA(1, rA1);
    LOADB(0, 0);
    for (int kc = 0; kc < 20; kc += 2) {
        const int p = (kc >> 1) & 1;
        *(uint4*)(&As[p][0][stsOff]) = rA0;
        *(uint4*)(&As[p][1][stsOff]) = rA1;
        LOADB(kc + 1, 1);
        if (kc + 2 < 20) { LOADA(kc + 2, rA0); LOADA(kc + 3, rA1); }
        __syncthreads();
        COMPUTE(As[p][0], 0);
        if (kc + 2 < 20) LOADB(kc + 2, 0);
        COMPUTE(As[p][1], 1);
    }
#undef LOADA
#undef LOADB
#undef COMPUTE

    // Epilogue: lane pair (l, l^1) exchanges to gather all 4 gates of a cell.
#pragma unroll
    for (int tm = 0; tm < 2; tm++) {
        int rbase = b0 + wm * 32 + tm * 16 + gr;
#pragma unroll
        for (int tn = 0; tn < 4; tn++) {
            float c0 = acc[tm][tn][0], c1 = acc[tm][tn][1];
            float c2 = acc[tm][tn][2], c3 = acc[tm][tn][3];
            float e0 = __shfl_xor_sync(0xffffffffu, c0, 1);
            float e1 = __shfl_xor_sync(0xffffffffu, c1, 1);
            float e2 = __shfl_xor_sync(0xffffffffu, c2, 1);
            float e3 = __shfl_xor_sync(0xffffffffu, c3, 1);
            float iv, fv, ov, gv;
            int brow;
            if ((q & 1) == 0) { iv = c0; fv = c1; ov = e0; gv = e1; brow = rbase; }
            else              { iv = e2; fv = e3; ov = c2; gv = c3; brow = rbase + 8; }
            int jj4 = wn * 32 + tn * 8 + (q >> 1) * 4;
            float4 bs = *(const float4*)&bsum[jj4];
            float gi = sigmf(iv + bs.x);
            float gf = sigmf(fv + bs.y);
            float go = sigmf(ov + bs.z);
            float gg = tanhf(gv + bs.w);
            int jg = j0 + (jj4 >> 2);
            int kp = (jg & ~31) + k2slot(jg & 31);   // store h perm32'd
            size_t ci = (size_t)brow * HN + jg;
            float cn = gf * cst[ci] + gi * gg;
            cst[ci] = cn;
            hout[(size_t)brow * HN + kp] = __float2half_rn(go * tanhf(cn));
        }
    }
}

// ============================================================================
// fc_kernel: y[b,s,v] = [hf(s)|hb(s)] . Wfc[v,:] + bfc[v]. K=1024 fp16,
// 32 chunks of 32. CTA 128 rows x 128 cols, 512 threads = 16 warps (4m x 4n),
// warp tile 32x32 (tm=2 m16 tiles!). A via smem (perm32 h), B direct LDG.
// ============================================================================
__global__ __launch_bounds__(512, 1) void fc_kernel(const float* __restrict__ bfc,
                                                    float* __restrict__ y) {
    __shared__ __align__(16) __half As[2][2][128 * 32];
    __shared__ float bsh[128];

    const int tid = threadIdx.x;
    const int s = blockIdx.x >> 2;
    const int b0r = (blockIdx.x & 3) * 128;

    const __half* Af = g_hs_f + (size_t)(s + 1) * BN * HN;
    const __half* Ab = g_hs_b + (size_t)(SN - s) * BN * HN;

    if (tid < 128) bsh[tid] = bfc[tid];

    const int lrow = tid >> 2, lseg = tid & 3;       // 8 halfs/thread/chunk
    const int w = tid >> 5, lane = tid & 31;
    const int wm = w >> 2, wn = w & 3;               // 4x4 warp grid, warp tile 32x32
    const int gr = lane >> 2, q = lane & 3;
    const int swz = (gr >> 1) & 3;
    const int stsOff = lrow * 32 + 8 * (lseg ^ ((lrow >> 1) & 3));
    const int aOffBase = wm * 1024 + gr * 32 + 8 * (q ^ swz);   // warp covers 32 rows

    const __half* afRow = Af + (size_t)(b0r + lrow) * HN;
    const __half* abRow = Ab + (size_t)(b0r + lrow) * HN;
    const __half* bPtr = g_wfc + (size_t)(wn * 32 + gr) * 1024 + q * 8;

    float acc[2][4][4];
#pragma unroll
    for (int i = 0; i < 2; i++)
#pragma unroll
        for (int jx = 0; jx < 4; jx++)
#pragma unroll
            for (int kx = 0; kx < 4; kx++) acc[i][jx][kx] = 0.f;

    uint4 bF[2][4], rA0, rA1;

#define LOADAFC(ch, dst)                                                              \
    {                                                                                 \
        const __half* src = ((ch) < 16) ? (afRow + (ch) * 32) : (abRow + ((ch) - 16) * 32); \
        dst = *(const uint4*)(src + lseg * 8);                                        \
    }
#define LOADBFC(ch, buf)                                                              \
    {                                                                                 \
        _Pragma("unroll")                                                             \
        for (int tn = 0; tn < 4; tn++)                                                \
            bF[buf][tn] = *(const uint4*)(bPtr + (size_t)tn * 8 * 1024 + (ch) * 32);  \
    }
#define COMPFC(S, bb)                                                                 \
    {                                                                                 \
        _Pragma("unroll")                                                             \
        for (int tm = 0; tm < 2; tm++) {                                              \
            const __half* base = (S) + tm * 512 + aOffBase;                           \
            uint4 A0 = *(const uint4*)(base);                                         \
            uint4 A1 = *(const uint4*)(base + 256);                                   \
            unsigned af0[4] = {A0.x, A1.x, A0.y, A1.y};                               \
            unsigned af1[4] = {A0.z, A1.z, A0.w, A1.w};                               \
            _Pragma("unroll")                                                         \
            for (int tn = 0; tn < 4; tn++) {                                          \
                unsigned bk0[2] = {bF[bb][tn].x, bF[bb][tn].y};                       \
                unsigned bk1[2] = {bF[bb][tn].z, bF[bb][tn].w};                       \
                mma_f16(acc[tm][tn], af0, bk0);                                       \
                mma_f16(acc[tm][tn], af1, bk1);                                       \
            }                                                                         \
        }                                                                             \
    }

    LOADAFC(0, rA0);
    LOADAFC(1, rA1);
    LOADBFC(0, 0);
    for (int kc = 0; kc < 32; kc += 2) {
        const int p = (kc >> 1) & 1;
        *(uint4*)(&As[p][0][stsOff]) = rA0;
        *(uint4*)(&As[p][1][stsOff]) = rA1;
        LOADBFC(kc + 1, 1);
        if (kc + 2 < 32) { LOADAFC(kc + 2, rA0); LOADAFC(kc + 3, rA1); }
        __syncthreads();
        COMPFC(As[p][0], 0);
        if (kc + 2 < 32) LOADBFC(kc + 2, 0);
        COMPFC(As[p][1], 1);
    }
#undef LOADAFC
#undef LOADBFC
#undef COMPFC

#pragma unroll
    for (int tm = 0; tm < 2; tm++) {
        int b = b0r + wm * 32 + tm * 16 + gr;
#pragma unroll
        for (int tn = 0; tn < 4; tn++) {
            int n0 = wn * 32 + tn * 8 + 2 * q;
            float2 w0 = make_float2(acc[tm][tn][0] + bsh[n0], acc[tm][tn][1] + bsh[n0 + 1]);
            *(float2*)(y + ((size_t)b * SN + s) * VN + n0) = w0;
            float2 w1 = make_float2(acc[tm][tn][2] + bsh[n0], acc[tm][tn][3] + bsh[n0 + 1]);
            *(float2*)(y + ((size_t)(b + 8) * SN + s) * VN + n0) = w1;
        }
    }
}

extern "C" void kernel_launch(void* const* d_in, const int* in_sizes, int n_in,
                              void* d_out, int out_size) {
    const int*   x    = (const int*)d_in[0];
    const float* Wx_f = (const float*)d_in[1];
    const float* Wh_f = (const float*)d_in[2];
    const float* bx_f = (const float*)d_in[3];
    const float* bh_f = (const float*)d_in[4];
    const float* Wx_b = (const float*)d_in[5];
    const float* Wh_b = (const float*)d_in[6];
    const float* bx_b = (const float*)d_in[7];
    const float* bh_b = (const float*)d_in[8];
    const float* Wfc  = (const float*)d_in[9];
    const float* bfc  = (const float*)d_in[10];
    float* y = (float*)d_out;

    init_kernel<<<2048, 256>>>();
    pack_w_kernel<<<(2 * 2048 * 640 + 255) / 256, 256>>>(Wh_f, Wx_f, Wh_b, Wx_b);
    pack_wfc_kernel<<<(VN * 1024 + 255) / 256, 256>>>(Wfc);

    // 256 sequential recurrence steps; both directions fused per launch.
    dim3 g(8, 16, 2);  // 8 batch tiles x 16 neuron tiles x 2 directions = 256 CTAs (2/SM)
    for (int t = 0; t < SN; t++)
        step_kernel<<<g, 256>>>(t, x, bx_f, bh_f, bx_b, bh_b);

    // final projection over all (s, b): 256 s x 4 batch tiles
    fc_kernel<<<1024, 512>>>(bfc, y);
}